// round 1
// baseline (speedup 1.0000x reference)
#include <cuda_runtime.h>
#include <cuda_bf16.h>
#include <math.h>

#define Bv 8
#define Sv 2048
#define Dv 320
#define NHv 5
#define HDv 64
#define FFv 864
#define NLv 6
#define NLOOPSv 8
#define TOK (Bv*Sv)
#define KSEL 1638

// ---------------- scratch (static device globals; no allocs) ----------------
__device__ float g_x[TOK*Dv];
__device__ float g_h[TOK*Dv];
__device__ float g_qkv[TOK*3*Dv];
__device__ float g_q[Bv*NHv*Sv*HDv];
__device__ float g_k[Bv*NHv*Sv*HDv];
__device__ float g_v[Bv*NHv*Sv*HDv];
__device__ float g_att[TOK*Dv];
__device__ float g_probs[TOK];
__device__ float g_wsel[TOK];
__device__ float g_g1[TOK*FFv];
__device__ float g_g2[TOK*FFv];

// ---------------- embedding + iter_emb ----------------
__global__ void k_embed(const int* __restrict__ ids, const int* __restrict__ iter,
                        const float* __restrict__ emb, const float* __restrict__ iter_emb) {
    int idx = blockIdx.x*256 + threadIdx.x;
    if (idx >= TOK*Dv) return;
    int t = idx / Dv, d = idx - t*Dv;
    float v = emb[(size_t)ids[t]*Dv + d];
    int it = iter[0];
    if (it < NLOOPSv) v += iter_emb[it*Dv + d];
    g_x[idx] = v;
}

// ---------------- rmsnorm (warp per token, D=320=32*10) ----------------
__global__ void k_rmsnorm(const float* __restrict__ in, const float* __restrict__ w,
                          float* __restrict__ out) {
    int gw = (blockIdx.x*256 + threadIdx.x) >> 5;
    int lane = threadIdx.x & 31;
    if (gw >= TOK) return;
    const float* xr = in + (size_t)gw*Dv;
    float v[10]; float ss = 0.f;
    #pragma unroll
    for (int i=0;i<10;i++){ v[i] = xr[lane+32*i]; ss = fmaf(v[i],v[i],ss); }
    #pragma unroll
    for (int o=16;o;o>>=1) ss += __shfl_xor_sync(0xffffffffu, ss, o);
    float inv = rsqrtf(ss*(1.f/Dv) + 1e-6f);
    float* orow = out + (size_t)gw*Dv;
    #pragma unroll
    for (int i=0;i<10;i++) orow[lane+32*i] = w[lane+32*i]*v[i]*inv;
}

// ---------------- fp32 GEMM: C[m][n] = rowscale[m]*sum_k A[m][k]*W[n][k] + addsrc ----------------
// BM=BN=128, BK=16, 256 threads, 8x8 microtile. M multiple of 128, K multiple of 16.
__global__ __launch_bounds__(256) void k_gemm(
    const float* __restrict__ A, const float* __restrict__ W, float* __restrict__ C,
    const float* __restrict__ addsrc, const float* __restrict__ rowscale,
    int M, int N, int K)
{
    __shared__ float As[16][132];
    __shared__ float Ws[16][132];
    int m0 = blockIdx.y*128, n0 = blockIdx.x*128;
    int tid = threadIdx.x;
    int ty = tid>>4, tx = tid&15;
    float acc[8][8];
    #pragma unroll
    for (int i=0;i<8;i++)
        #pragma unroll
        for (int j=0;j<8;j++) acc[i][j] = 0.f;

    int lrow = tid>>2;
    int c4   = (tid&3)*4;
    for (int k0=0;k0<K;k0+=16) {
        #pragma unroll
        for (int half=0; half<2; half++) {
            int r = lrow + half*64;
            float4 av = *(const float4*)(A + (size_t)(m0+r)*K + k0 + c4);
            As[c4+0][r]=av.x; As[c4+1][r]=av.y; As[c4+2][r]=av.z; As[c4+3][r]=av.w;
            int n = n0 + r;
            float4 wv = make_float4(0.f,0.f,0.f,0.f);
            if (n < N) wv = *(const float4*)(W + (size_t)n*K + k0 + c4);
            Ws[c4+0][r]=wv.x; Ws[c4+1][r]=wv.y; Ws[c4+2][r]=wv.z; Ws[c4+3][r]=wv.w;
        }
        __syncthreads();
        #pragma unroll
        for (int kk=0;kk<16;kk++) {
            float4 a0 = *(const float4*)&As[kk][ty*8];
            float4 a1 = *(const float4*)&As[kk][ty*8+4];
            float4 b0 = *(const float4*)&Ws[kk][tx*8];
            float4 b1 = *(const float4*)&Ws[kk][tx*8+4];
            float a[8] = {a0.x,a0.y,a0.z,a0.w,a1.x,a1.y,a1.z,a1.w};
            float b[8] = {b0.x,b0.y,b0.z,b0.w,b1.x,b1.y,b1.z,b1.w};
            #pragma unroll
            for (int i=0;i<8;i++)
                #pragma unroll
                for (int j=0;j<8;j++)
                    acc[i][j] = fmaf(a[i], b[j], acc[i][j]);
        }
        __syncthreads();
    }
    #pragma unroll
    for (int i=0;i<8;i++) {
        int m = m0 + ty*8 + i;
        float rs = rowscale ? rowscale[m] : 1.f;
        #pragma unroll
        for (int j=0;j<8;j++) {
            int n = n0 + tx*8 + j;
            if (n < N) {
                float val = acc[i][j]*rs;
                if (addsrc) val += addsrc[(size_t)m*N + n];
                C[(size_t)m*N + n] = val;
            }
        }
    }
}

// ---------------- RoPE + [B,S,3D] -> [B,H,S,HD] split ----------------
__global__ void k_rope() {
    int idx = blockIdx.x*256 + threadIdx.x;
    if (idx >= TOK*Dv) return;
    int t = idx / Dv;
    int rem = idx - t*Dv;
    int h = rem >> 6, d = rem & 63;
    int s = t & (Sv-1), b = t >> 11;
    const float* base = g_qkv + (size_t)t*(3*Dv) + h*HDv;
    float qv = base[d], kv = base[Dv + d], vv = base[2*Dv + d];
    int i2 = d & 31;
    // freq = 10000^(-2*i2/64)
    float freq = expf(-(float)(2*i2) * (9.210340371976184f/64.0f));
    float ang = (float)s * freq;
    float sn, cs; sincosf(ang, &sn, &cs);
    float qr, kr;
    if (d < 32) { qr = -base[d+32];      kr = -base[Dv+d+32]; }
    else        { qr =  base[d-32];      kr =  base[Dv+d-32]; }
    size_t o = (((size_t)b*NHv + h)*Sv + s)*HDv + d;
    g_q[o] = qv*cs + qr*sn;
    g_k[o] = kv*cs + kr*sn;
    g_v[o] = vv;
}

// ---------------- causal flash attention, 64 queries/block ----------------
__global__ __launch_bounds__(256) void k_attn() {
    extern __shared__ float sm[];
    float* Qs = sm;                 // [64][64]
    float* Ks = sm + 64*64;         // [64] stride 65
    float* Ps = Ks + 64*65;         // [64] stride 65
    float* Vs = Ps + 64*65;         // [64] stride 68 (float4-aligned)
    int qt = blockIdx.x, h = blockIdx.y, b = blockIdx.z;
    int tid = threadIdx.x;
    const size_t headoff = ((size_t)b*NHv + h)*(size_t)Sv*HDv;
    const float* Qg = g_q + headoff + (size_t)qt*64*64;
    #pragma unroll
    for (int it=0; it<16; it++) Qs[tid + it*256] = Qg[tid + it*256];

    int r = tid >> 2, c = tid & 3;      // softmax/output mapping
    int rg = tid >> 4, jg = tid & 15;   // score microtile mapping
    float o[16];
    #pragma unroll
    for (int i=0;i<16;i++) o[i]=0.f;
    float m_run = -1e30f, l = 0.f;

    for (int t0 = 0; t0 <= qt; t0++) {
        const float* Kg = g_k + headoff + (size_t)t0*64*64;
        const float* Vg = g_v + headoff + (size_t)t0*64*64;
        __syncthreads();   // previous tile fully consumed
        #pragma unroll
        for (int it=0; it<16; it++) {
            int idx = tid + it*256;
            int row = idx >> 6, dd = idx & 63;
            Ks[row*65+dd] = Kg[idx];
            Vs[row*68+dd] = Vg[idx];
        }
        __syncthreads();

        // pass1: S = Q K^T (4x4 microtile per thread)
        {
            float sacc[4][4];
            #pragma unroll
            for (int i=0;i<4;i++)
                #pragma unroll
                for (int j=0;j<4;j++) sacc[i][j] = 0.f;
            #pragma unroll 8
            for (int dd=0; dd<64; dd++) {
                float a[4], bb[4];
                #pragma unroll
                for (int i=0;i<4;i++) a[i]  = Qs[(rg*4+i)*64 + dd];
                #pragma unroll
                for (int j=0;j<4;j++) bb[j] = Ks[(jg*4+j)*65 + dd];
                #pragma unroll
                for (int i=0;i<4;i++)
                    #pragma unroll
                    for (int j=0;j<4;j++) sacc[i][j] = fmaf(a[i], bb[j], sacc[i][j]);
            }
            bool diag = (t0 == qt);
            #pragma unroll
            for (int i=0;i<4;i++) {
                int rr = rg*4+i;
                #pragma unroll
                for (int j=0;j<4;j++) {
                    int jj = jg*4+j;
                    float s = sacc[i][j]*0.125f;
                    if (diag && jj > rr) s = -1e30f;
                    Ps[rr*65 + jj] = s;
                }
            }
        }
        __syncthreads();

        // pass2: online softmax (4 lanes per row, 16 cols each)
        float mt = -1e30f;
        #pragma unroll
        for (int jj=c; jj<64; jj+=4) mt = fmaxf(mt, Ps[r*65+jj]);
        mt = fmaxf(mt, __shfl_xor_sync(0xffffffffu, mt, 1));
        mt = fmaxf(mt, __shfl_xor_sync(0xffffffffu, mt, 2));
        float m_new = fmaxf(m_run, mt);
        float scale = expf(m_run - m_new);
        l *= scale;
        #pragma unroll
        for (int i=0;i<16;i++) o[i] *= scale;
        m_run = m_new;
        #pragma unroll
        for (int jj=c; jj<64; jj+=4) {
            float p = expf(Ps[r*65+jj] - m_new);
            Ps[r*65+jj] = p;
            l += p;
        }
        __syncwarp();

        // pass3: O += P V   (each lane owns 16 dims: c*16..c*16+15)
        const float* vb = Vs + c*16;
        #pragma unroll 4
        for (int j=0;j<64;j++) {
            float p = Ps[r*65+j];
            const float4* vr = (const float4*)(vb + j*68);
            float4 v0 = vr[0], v1 = vr[1], v2 = vr[2], v3 = vr[3];
            o[0]  = fmaf(p, v0.x, o[0]);  o[1]  = fmaf(p, v0.y, o[1]);
            o[2]  = fmaf(p, v0.z, o[2]);  o[3]  = fmaf(p, v0.w, o[3]);
            o[4]  = fmaf(p, v1.x, o[4]);  o[5]  = fmaf(p, v1.y, o[5]);
            o[6]  = fmaf(p, v1.z, o[6]);  o[7]  = fmaf(p, v1.w, o[7]);
            o[8]  = fmaf(p, v2.x, o[8]);  o[9]  = fmaf(p, v2.y, o[9]);
            o[10] = fmaf(p, v2.z, o[10]); o[11] = fmaf(p, v2.w, o[11]);
            o[12] = fmaf(p, v3.x, o[12]); o[13] = fmaf(p, v3.y, o[13]);
            o[14] = fmaf(p, v3.z, o[14]); o[15] = fmaf(p, v3.w, o[15]);
        }
    }
    l += __shfl_xor_sync(0xffffffffu, l, 1);
    l += __shfl_xor_sync(0xffffffffu, l, 2);
    float inv = 1.f/l;
    float* orow = g_att + (size_t)(b*Sv + qt*64 + r)*Dv + h*HDv + c*16;
    #pragma unroll
    for (int dd=0;dd<16;dd++) orow[dd] = o[dd]*inv;
}

// ---------------- router: sigmoid(x . w) per token ----------------
__global__ void k_router(const float* __restrict__ rw) {
    int gw = (blockIdx.x*256 + threadIdx.x) >> 5;
    int lane = threadIdx.x & 31;
    if (gw >= TOK) return;
    const float* xr = g_x + (size_t)gw*Dv;
    float s = 0.f;
    #pragma unroll
    for (int i=0;i<10;i++) s = fmaf(xr[lane+32*i], rw[lane+32*i], s);
    #pragma unroll
    for (int o=16;o;o>>=1) s += __shfl_xor_sync(0xffffffffu, s, o);
    if (lane==0) g_probs[gw] = 1.f/(1.f+expf(-s));
}

// ---------------- exact top-k by rank counting (matches jax tie-breaking) ----------------
__global__ __launch_bounds__(256) void k_topk() {
    __shared__ float p[Sv];
    int b = blockIdx.x, part = blockIdx.y;
    int tid = threadIdx.x;
    for (int i=tid;i<Sv;i+=256) p[i] = g_probs[b*Sv+i];
    __syncthreads();
    int i = part*256 + tid;
    float pi = p[i];
    int cnt = 0;
    #pragma unroll 8
    for (int j=0;j<Sv;j++) {
        float pj = p[j];
        cnt += (pj > pi) || (pj == pi && j < i);
    }
    g_wsel[b*Sv+i] = (cnt < KSEL) ? pi : 0.f;
}

// ---------------- silu(gate)*up ----------------
__global__ void k_silu() {
    int idx = blockIdx.x*256+threadIdx.x;
    if (idx >= TOK*FFv) return;
    float g = g_g1[idx], u = g_g2[idx];
    g_g1[idx] = g * u / (1.f + expf(-g));
}

// ---------------- driver ----------------
extern "C" void kernel_launch(void* const* d_in, const int* in_sizes, int n_in,
                              void* d_out, int out_size) {
    const int*   ids        = (const int*)d_in[0];
    const int*   iter       = (const int*)d_in[1];
    const float* emb        = (const float*)d_in[2];
    const float* iter_emb   = (const float*)d_in[3];
    const float* attn_norm  = (const float*)d_in[4];
    const float* Wqkv       = (const float*)d_in[5];
    const float* wo         = (const float*)d_in[6];
    const float* router     = (const float*)d_in[7];
    const float* mlp_norm   = (const float*)d_in[8];
    const float* gatew      = (const float*)d_in[9];
    const float* upw        = (const float*)d_in[10];
    const float* downw      = (const float*)d_in[11];
    const float* final_norm = (const float*)d_in[12];
    float* out = (float*)d_out;

    float *xp,*hp,*qkvp,*attp,*g1p,*g2p,*wselp;
    cudaGetSymbolAddress((void**)&xp,   g_x);
    cudaGetSymbolAddress((void**)&hp,   g_h);
    cudaGetSymbolAddress((void**)&qkvp, g_qkv);
    cudaGetSymbolAddress((void**)&attp, g_att);
    cudaGetSymbolAddress((void**)&g1p,  g_g1);
    cudaGetSymbolAddress((void**)&g2p,  g_g2);
    cudaGetSymbolAddress((void**)&wselp,g_wsel);

    cudaFuncSetAttribute(k_attn, cudaFuncAttributeMaxDynamicSharedMemorySize, 67072);

    k_embed<<<(TOK*Dv+255)/256, 256>>>(ids, iter, emb, iter_emb);

    dim3 gq((3*Dv+127)/128, TOK/128);
    dim3 g320((Dv+127)/128, TOK/128);
    dim3 gff((FFv+127)/128, TOK/128);

    for (int l=0;l<NLv;l++) {
        k_rmsnorm<<<TOK/8, 256>>>(xp, attn_norm + (size_t)l*Dv, hp);
        k_gemm<<<gq, 256>>>(hp, Wqkv + (size_t)l*3*Dv*Dv, qkvp, nullptr, nullptr, TOK, 3*Dv, Dv);
        k_rope<<<(TOK*Dv+255)/256, 256>>>();
        k_attn<<<dim3(Sv/64, NHv, Bv), 256, 67072>>>();
        k_gemm<<<g320, 256>>>(attp, wo + (size_t)l*Dv*Dv, xp, xp, nullptr, TOK, Dv, Dv);
        k_router<<<TOK/8, 256>>>(router + (size_t)l*Dv);
        k_topk<<<dim3(Bv, Sv/256), 256>>>();
        k_rmsnorm<<<TOK/8, 256>>>(xp, mlp_norm + (size_t)l*Dv, hp);
        k_gemm<<<gff, 256>>>(hp, gatew + (size_t)l*FFv*Dv, g1p, nullptr, nullptr, TOK, FFv, Dv);
        k_gemm<<<gff, 256>>>(hp, upw   + (size_t)l*FFv*Dv, g2p, nullptr, nullptr, TOK, FFv, Dv);
        k_silu<<<(TOK*FFv+255)/256, 256>>>();
        k_gemm<<<g320, 256>>>(g1p, downw + (size_t)l*Dv*FFv, xp, xp, wselp, TOK, Dv, FFv);
    }
    k_rmsnorm<<<TOK/8, 256>>>(xp, final_norm, out);
}

// round 2
// speedup vs baseline: 1.2572x; 1.2572x over previous
#include <cuda_runtime.h>
#include <cuda_bf16.h>
#include <math.h>

#define Bv 8
#define Sv 2048
#define Dv 320
#define NHv 5
#define HDv 64
#define FFv 864
#define NLv 6
#define NLOOPSv 8
#define TOK (Bv*Sv)
#define KSEL 1638

// ---------------- scratch (static device globals; no allocs) ----------------
__device__ float g_x[TOK*Dv];
__device__ float g_h[TOK*Dv];       // tf32 bits (GEMM A input)
__device__ float g_qkv[TOK*3*Dv];
__device__ float g_q[Bv*NHv*Sv*HDv];
__device__ float g_k[Bv*NHv*Sv*HDv];
__device__ float g_v[Bv*NHv*Sv*HDv];
__device__ float g_att[TOK*Dv];     // tf32 bits
__device__ float g_probs[TOK];
__device__ float g_wsel[TOK];
__device__ float g_g1[TOK*FFv];     // gate fp32
__device__ float g_g2[TOK*FFv];     // swiglu act, tf32 bits

// converted tf32 weights
#define OFF_QKV  0
#define OFF_WO   1843200
#define OFF_GATE 2457600
#define OFF_UP   4116480
#define OFF_DOWN 5775360
#define TOTW     7434240
__device__ float g_wt[TOTW];

__device__ __forceinline__ float to_tf32(float x){
    unsigned u; asm("cvt.rna.tf32.f32 %0, %1;" : "=r"(u) : "f"(x));
    return __uint_as_float(u);
}

// ---------------- generic f32 -> tf32-bits conversion ----------------
__global__ void k_cvt(const float* __restrict__ in, float* __restrict__ out, int n){
    int i = blockIdx.x*256 + threadIdx.x;
    if (i < n) out[i] = to_tf32(in[i]);
}

// ---------------- embedding + iter_emb ----------------
__global__ void k_embed(const int* __restrict__ ids, const int* __restrict__ iter,
                        const float* __restrict__ emb, const float* __restrict__ iter_emb) {
    int idx = blockIdx.x*256 + threadIdx.x;
    if (idx >= TOK*Dv) return;
    int t = idx / Dv, d = idx - t*Dv;
    float v = emb[(size_t)ids[t]*Dv + d];
    int it = iter[0];
    if (it < NLOOPSv) v += iter_emb[it*Dv + d];
    g_x[idx] = v;
}

// ---------------- rmsnorm (warp per token, D=320=32*10) ----------------
__global__ void k_rmsnorm(const float* __restrict__ in, const float* __restrict__ w,
                          float* __restrict__ out, int tf32out) {
    int gw = (blockIdx.x*256 + threadIdx.x) >> 5;
    int lane = threadIdx.x & 31;
    if (gw >= TOK) return;
    const float* xr = in + (size_t)gw*Dv;
    float v[10]; float ss = 0.f;
    #pragma unroll
    for (int i=0;i<10;i++){ v[i] = xr[lane+32*i]; ss = fmaf(v[i],v[i],ss); }
    #pragma unroll
    for (int o=16;o;o>>=1) ss += __shfl_xor_sync(0xffffffffu, ss, o);
    float inv = rsqrtf(ss*(1.f/Dv) + 1e-6f);
    float* orow = out + (size_t)gw*Dv;
    #pragma unroll
    for (int i=0;i<10;i++){
        float val = w[lane+32*i]*v[i]*inv;
        orow[lane+32*i] = tf32out ? to_tf32(val) : val;
    }
}

// ---------------- tf32 tensor-core GEMM ----------------
// C[m][n] = epilogue( sum_k A[m][k]*W[n][k] ), A,W pre-converted tf32 bits.
// BM=BN=128, BK=32, 256 threads = 8 warps (4m x 2n), each warp 32x64.
// smem layout: row-major [row][k] with stride 36 floats (pad 4) -> conflict-free frags.
#define CPA(dst, src) asm volatile("cp.async.cg.shared.global [%0], [%1], 16;\n" :: "r"(dst), "l"(src))
#define CPAZ(dst, src, sz) asm volatile("cp.async.cg.shared.global [%0], [%1], 16, %2;\n" :: "r"(dst), "l"(src), "r"(sz))

__global__ __launch_bounds__(256) void k_gemm_tc(
    const float* __restrict__ A, const float* __restrict__ W, float* __restrict__ C,
    const float* __restrict__ aux, const float* __restrict__ rowscale,
    int M, int N, int K, int ep)
{
    extern __shared__ float sm[];
    const int SA = 128*36;
    // buffers: As0, As1, Ws0, Ws1
    unsigned base = (unsigned)__cvta_generic_to_shared(sm);
    unsigned Asb[2] = { base, base + SA*4u };
    unsigned Wsb[2] = { base + 2u*SA*4u, base + 3u*SA*4u };
    float* Asp[2] = { sm, sm + SA };
    float* Wsp[2] = { sm + 2*SA, sm + 3*SA };

    int tid = threadIdx.x;
    int lane = tid & 31, warp = tid >> 5;
    int wm = warp >> 1, wn = warp & 1;
    int m0 = blockIdx.y*128, n0 = blockIdx.x*128;

    int lrow = tid >> 3;        // 0..31
    int c16  = tid & 7;         // 16B chunk within row
    const float* Ag = A + (size_t)(m0 + lrow)*K + c16*4;
    // W row with guard (clamp addr, zero-fill via src-size)
    int wr0 = n0 + lrow;

    float acc[2][8][4];
    #pragma unroll
    for (int i=0;i<2;i++)
        #pragma unroll
        for (int j=0;j<8;j++)
            #pragma unroll
            for (int c=0;c<4;c++) acc[i][j][c]=0.f;

    int nkb = K >> 5;

    // ---- tile loader ----
    #define LOADTILE(buf, k0) do {                                              \
        _Pragma("unroll")                                                       \
        for (int i=0;i<4;i++){                                                  \
            int r = lrow + 32*i;                                                \
            unsigned d = Asb[buf] + (unsigned)((r*36 + c16*4)*4);               \
            CPA(d, Ag + (size_t)(32*i)*K + (k0));                               \
        }                                                                       \
        _Pragma("unroll")                                                       \
        for (int i=0;i<4;i++){                                                  \
            int r = lrow + 32*i;                                                \
            int wr = wr0 + 32*i;                                                \
            unsigned sz = (wr < N) ? 16u : 0u;                                  \
            const float* src = W + (size_t)(wr < N ? wr : 0)*K + (k0) + c16*4;  \
            unsigned d = Wsb[buf] + (unsigned)((r*36 + c16*4)*4);               \
            CPAZ(d, src, sz);                                                   \
        }                                                                       \
    } while(0)

    LOADTILE(0, 0);
    asm volatile("cp.async.commit_group;\n");

    int buf = 0;
    int lr = lane >> 2, lc = lane & 3;
    for (int kb=0; kb<nkb; kb++){
        if (kb+1 < nkb){
            LOADTILE(buf^1, (kb+1)*32);
            asm volatile("cp.async.commit_group;\n");
            asm volatile("cp.async.wait_group 1;\n");
        } else {
            asm volatile("cp.async.wait_group 0;\n");
        }
        __syncthreads();

        const float* Ab = Asp[buf];
        const float* Wb = Wsp[buf];
        #pragma unroll
        for (int ks=0; ks<4; ks++){
            unsigned a[2][4], b[8][2];
            #pragma unroll
            for (int mf=0; mf<2; mf++){
                const float* p = Ab + (wm*32 + mf*16 + lr)*36 + ks*8 + lc;
                a[mf][0] = __float_as_uint(p[0]);
                a[mf][1] = __float_as_uint(p[8*36]);
                a[mf][2] = __float_as_uint(p[4]);
                a[mf][3] = __float_as_uint(p[8*36+4]);
            }
            #pragma unroll
            for (int nf=0; nf<8; nf++){
                const float* p = Wb + (wn*64 + nf*8 + lr)*36 + ks*8 + lc;
                b[nf][0] = __float_as_uint(p[0]);
                b[nf][1] = __float_as_uint(p[4]);
            }
            #pragma unroll
            for (int mf=0; mf<2; mf++)
                #pragma unroll
                for (int nf=0; nf<8; nf++)
                    asm volatile(
                        "mma.sync.aligned.m16n8k8.row.col.f32.tf32.tf32.f32 "
                        "{%0,%1,%2,%3},{%4,%5,%6,%7},{%8,%9},{%0,%1,%2,%3};\n"
                        : "+f"(acc[mf][nf][0]),"+f"(acc[mf][nf][1]),
                          "+f"(acc[mf][nf][2]),"+f"(acc[mf][nf][3])
                        : "r"(a[mf][0]),"r"(a[mf][1]),"r"(a[mf][2]),"r"(a[mf][3]),
                          "r"(b[nf][0]),"r"(b[nf][1]));
        }
        buf ^= 1;
        __syncthreads();
    }

    // ---- epilogue ----
    #pragma unroll
    for (int mf=0; mf<2; mf++){
        #pragma unroll
        for (int nf=0; nf<8; nf++){
            int mbase = m0 + wm*32 + mf*16 + lr;
            int nbase = n0 + wn*64 + nf*8 + lc*2;
            #pragma unroll
            for (int c=0;c<4;c++){
                int m = mbase + (c>=2 ? 8 : 0);
                int n = nbase + (c&1);
                if (n < N){
                    size_t o = (size_t)m*N + n;
                    float v = acc[mf][nf][c], r;
                    if (ep==0) r = v;
                    else if (ep==1) r = aux[o] + v;
                    else if (ep==2) r = aux[o] + rowscale[m]*v;
                    else { float g = aux[o]; r = to_tf32(g * v / (1.f + expf(-g))); }
                    C[o] = r;
                }
            }
        }
    }
}

// ---------------- RoPE + [B,S,3D] -> [B,H,S,HD] split ----------------
__global__ void k_rope() {
    int idx = blockIdx.x*256 + threadIdx.x;
    if (idx >= TOK*Dv) return;
    int t = idx / Dv;
    int rem = idx - t*Dv;
    int h = rem >> 6, d = rem & 63;
    int s = t & (Sv-1), b = t >> 11;
    const float* base = g_qkv + (size_t)t*(3*Dv) + h*HDv;
    float qv = base[d], kv = base[Dv + d], vv = base[2*Dv + d];
    int i2 = d & 31;
    float freq = expf(-(float)(2*i2) * (9.210340371976184f/64.0f));
    float ang = (float)s * freq;
    float sn, cs; sincosf(ang, &sn, &cs);
    float qr, kr;
    if (d < 32) { qr = -base[d+32];      kr = -base[Dv+d+32]; }
    else        { qr =  base[d-32];      kr =  base[Dv+d-32]; }
    size_t o = (((size_t)b*NHv + h)*Sv + s)*HDv + d;
    g_q[o] = qv*cs + qr*sn;
    g_k[o] = kv*cs + kr*sn;
    g_v[o] = vv;
}

// ---------------- causal flash attention, 64 queries/block ----------------
__global__ __launch_bounds__(256) void k_attn() {
    extern __shared__ float sm[];
    float* Qs = sm;                 // [64][64]
    float* Ks = sm + 64*64;         // stride 65
    float* Ps = Ks + 64*65;         // stride 65
    float* Vs = Ps + 64*65;         // stride 68
    int qt = blockIdx.x, h = blockIdx.y, b = blockIdx.z;
    int tid = threadIdx.x;
    const size_t headoff = ((size_t)b*NHv + h)*(size_t)Sv*HDv;
    const float* Qg = g_q + headoff + (size_t)qt*64*64;
    #pragma unroll
    for (int it=0; it<16; it++) Qs[tid + it*256] = Qg[tid + it*256];

    int r = tid >> 2, c = tid & 3;
    int rg = tid >> 4, jg = tid & 15;
    float o[16];
    #pragma unroll
    for (int i=0;i<16;i++) o[i]=0.f;
    float m_run = -1e30f, l = 0.f;

    for (int t0 = 0; t0 <= qt; t0++) {
        const float* Kg = g_k + headoff + (size_t)t0*64*64;
        const float* Vg = g_v + headoff + (size_t)t0*64*64;
        __syncthreads();
        #pragma unroll
        for (int it=0; it<16; it++) {
            int idx = tid + it*256;
            int row = idx >> 6, dd = idx & 63;
            Ks[row*65+dd] = Kg[idx];
            Vs[row*68+dd] = Vg[idx];
        }
        __syncthreads();

        {
            float sacc[4][4];
            #pragma unroll
            for (int i=0;i<4;i++)
                #pragma unroll
                for (int j=0;j<4;j++) sacc[i][j] = 0.f;
            #pragma unroll 8
            for (int dd=0; dd<64; dd++) {
                float a[4], bb[4];
                #pragma unroll
                for (int i=0;i<4;i++) a[i]  = Qs[(rg*4+i)*64 + dd];
                #pragma unroll
                for (int j=0;j<4;j++) bb[j] = Ks[(jg*4+j)*65 + dd];
                #pragma unroll
                for (int i=0;i<4;i++)
                    #pragma unroll
                    for (int j=0;j<4;j++) sacc[i][j] = fmaf(a[i], bb[j], sacc[i][j]);
            }
            bool diag = (t0 == qt);
            #pragma unroll
            for (int i=0;i<4;i++) {
                int rr = rg*4+i;
                #pragma unroll
                for (int j=0;j<4;j++) {
                    int jj = jg*4+j;
                    float s = sacc[i][j]*0.125f;
                    if (diag && jj > rr) s = -1e30f;
                    Ps[rr*65 + jj] = s;
                }
            }
        }
        __syncthreads();

        float mt = -1e30f;
        #pragma unroll
        for (int jj=c; jj<64; jj+=4) mt = fmaxf(mt, Ps[r*65+jj]);
        mt = fmaxf(mt, __shfl_xor_sync(0xffffffffu, mt, 1));
        mt = fmaxf(mt, __shfl_xor_sync(0xffffffffu, mt, 2));
        float m_new = fmaxf(m_run, mt);
        float scale = expf(m_run - m_new);
        l *= scale;
        #pragma unroll
        for (int i=0;i<16;i++) o[i] *= scale;
        m_run = m_new;
        #pragma unroll
        for (int jj=c; jj<64; jj+=4) {
            float p = expf(Ps[r*65+jj] - m_new);
            Ps[r*65+jj] = p;
            l += p;
        }
        __syncwarp();

        const float* vb = Vs + c*16;
        #pragma unroll 4
        for (int j=0;j<64;j++) {
            float p = Ps[r*65+j];
            const float4* vr = (const float4*)(vb + j*68);
            float4 v0 = vr[0], v1 = vr[1], v2 = vr[2], v3 = vr[3];
            o[0]  = fmaf(p, v0.x, o[0]);  o[1]  = fmaf(p, v0.y, o[1]);
            o[2]  = fmaf(p, v0.z, o[2]);  o[3]  = fmaf(p, v0.w, o[3]);
            o[4]  = fmaf(p, v1.x, o[4]);  o[5]  = fmaf(p, v1.y, o[5]);
            o[6]  = fmaf(p, v1.z, o[6]);  o[7]  = fmaf(p, v1.w, o[7]);
            o[8]  = fmaf(p, v2.x, o[8]);  o[9]  = fmaf(p, v2.y, o[9]);
            o[10] = fmaf(p, v2.z, o[10]); o[11] = fmaf(p, v2.w, o[11]);
            o[12] = fmaf(p, v3.x, o[12]); o[13] = fmaf(p, v3.y, o[13]);
            o[14] = fmaf(p, v3.z, o[14]); o[15] = fmaf(p, v3.w, o[15]);
        }
    }
    l += __shfl_xor_sync(0xffffffffu, l, 1);
    l += __shfl_xor_sync(0xffffffffu, l, 2);
    float inv = 1.f/l;
    float* orow = g_att + (size_t)(b*Sv + qt*64 + r)*Dv + h*HDv + c*16;
    #pragma unroll
    for (int dd=0;dd<16;dd++) orow[dd] = to_tf32(o[dd]*inv);
}

// ---------------- router: sigmoid(x . w) per token ----------------
__global__ void k_router(const float* __restrict__ rw) {
    int gw = (blockIdx.x*256 + threadIdx.x) >> 5;
    int lane = threadIdx.x & 31;
    if (gw >= TOK) return;
    const float* xr = g_x + (size_t)gw*Dv;
    float s = 0.f;
    #pragma unroll
    for (int i=0;i<10;i++) s = fmaf(xr[lane+32*i], rw[lane+32*i], s);
    #pragma unroll
    for (int o=16;o;o>>=1) s += __shfl_xor_sync(0xffffffffu, s, o);
    if (lane==0) g_probs[gw] = 1.f/(1.f+expf(-s));
}

// ---------------- exact top-k by rank counting ----------------
__global__ __launch_bounds__(256) void k_topk() {
    __shared__ float p[Sv];
    int b = blockIdx.x, part = blockIdx.y;
    int tid = threadIdx.x;
    for (int i=tid;i<Sv;i+=256) p[i] = g_probs[b*Sv+i];
    __syncthreads();
    int i = part*256 + tid;
    float pi = p[i];
    int cnt = 0;
    #pragma unroll 8
    for (int j=0;j<Sv;j++) {
        float pj = p[j];
        cnt += (pj > pi) || (pj == pi && j < i);
    }
    g_wsel[b*Sv+i] = (cnt < KSEL) ? pi : 0.f;
}

// ---------------- driver ----------------
extern "C" void kernel_launch(void* const* d_in, const int* in_sizes, int n_in,
                              void* d_out, int out_size) {
    const int*   ids        = (const int*)d_in[0];
    const int*   iter       = (const int*)d_in[1];
    const float* emb        = (const float*)d_in[2];
    const float* iter_emb   = (const float*)d_in[3];
    const float* attn_norm  = (const float*)d_in[4];
    const float* Wqkv       = (const float*)d_in[5];
    const float* wo         = (const float*)d_in[6];
    const float* router     = (const float*)d_in[7];
    const float* mlp_norm   = (const float*)d_in[8];
    const float* gatew      = (const float*)d_in[9];
    const float* upw        = (const float*)d_in[10];
    const float* downw      = (const float*)d_in[11];
    const float* final_norm = (const float*)d_in[12];
    float* out = (float*)d_out;

    float *xp,*hp,*qkvp,*attp,*g1p,*g2p,*wselp,*wtp;
    cudaGetSymbolAddress((void**)&xp,   g_x);
    cudaGetSymbolAddress((void**)&hp,   g_h);
    cudaGetSymbolAddress((void**)&qkvp, g_qkv);
    cudaGetSymbolAddress((void**)&attp, g_att);
    cudaGetSymbolAddress((void**)&g1p,  g_g1);
    cudaGetSymbolAddress((void**)&g2p,  g_g2);
    cudaGetSymbolAddress((void**)&wselp,g_wsel);
    cudaGetSymbolAddress((void**)&wtp,  g_wt);

    cudaFuncSetAttribute(k_attn, cudaFuncAttributeMaxDynamicSharedMemorySize, 67072);
    cudaFuncSetAttribute(k_gemm_tc, cudaFuncAttributeMaxDynamicSharedMemorySize, 73728);

    // weight conversion to tf32 (once per call)
    k_cvt<<<(1843200+255)/256,256>>>(Wqkv,  wtp+OFF_QKV,  1843200);
    k_cvt<<<(614400+255)/256, 256>>>(wo,    wtp+OFF_WO,   614400);
    k_cvt<<<(1658880+255)/256,256>>>(gatew, wtp+OFF_GATE, 1658880);
    k_cvt<<<(1658880+255)/256,256>>>(upw,   wtp+OFF_UP,   1658880);
    k_cvt<<<(1658880+255)/256,256>>>(downw, wtp+OFF_DOWN, 1658880);

    k_embed<<<(TOK*Dv+255)/256, 256>>>(ids, iter, emb, iter_emb);

    dim3 gq((3*Dv+127)/128, TOK/128);
    dim3 g320((Dv+127)/128, TOK/128);
    dim3 gff((FFv+127)/128, TOK/128);
    const int SMEMG = 73728;

    for (int l=0;l<NLv;l++) {
        k_rmsnorm<<<TOK/8, 256>>>(xp, attn_norm + (size_t)l*Dv, hp, 1);
        k_gemm_tc<<<gq, 256, SMEMG>>>(hp, wtp+OFF_QKV + (size_t)l*960*320, qkvp,
                                      nullptr, nullptr, TOK, 3*Dv, Dv, 0);
        k_rope<<<(TOK*Dv+255)/256, 256>>>();
        k_attn<<<dim3(Sv/64, NHv, Bv), 256, 67072>>>();
        k_gemm_tc<<<g320, 256, SMEMG>>>(attp, wtp+OFF_WO + (size_t)l*320*320, xp,
                                        xp, nullptr, TOK, Dv, Dv, 1);
        k_router<<<TOK/8, 256>>>(router + (size_t)l*Dv);
        k_topk<<<dim3(Bv, Sv/256), 256>>>();
        k_rmsnorm<<<TOK/8, 256>>>(xp, mlp_norm + (size_t)l*Dv, hp, 1);
        k_gemm_tc<<<gff, 256, SMEMG>>>(hp, wtp+OFF_GATE + (size_t)l*FFv*320, g1p,
                                       nullptr, nullptr, TOK, FFv, Dv, 0);
        k_gemm_tc<<<gff, 256, SMEMG>>>(hp, wtp+OFF_UP + (size_t)l*FFv*320, g2p,
                                       g1p, nullptr, TOK, FFv, Dv, 3);   // swiglu fused, tf32 out
        k_gemm_tc<<<g320, 256, SMEMG>>>(g2p, wtp+OFF_DOWN + (size_t)l*320*FFv, xp,
                                        xp, wselp, TOK, Dv, FFv, 2);
    }
    k_rmsnorm<<<TOK/8, 256>>>(xp, final_norm, out, 0);
}

// round 3
// speedup vs baseline: 3.3726x; 2.6826x over previous
#include <cuda_runtime.h>
#include <cuda_bf16.h>
#include <math.h>

#define Bv 8
#define Sv 2048
#define Dv 320
#define NHv 5
#define HDv 64
#define FFv 864
#define NLv 6
#define NLOOPSv 8
#define TOK (Bv*Sv)
#define KSEL 1638

// ---------------- scratch ----------------
__device__ float g_x[TOK*Dv];
__device__ float g_h[TOK*Dv];       // tf32 bits
__device__ float g_qkv[TOK*3*Dv];
__device__ float g_q[Bv*NHv*Sv*HDv];   // tf32 bits [B][H][S][HD]
__device__ float g_k[Bv*NHv*Sv*HDv];   // tf32 bits [B][H][S][HD]
__device__ float g_v[Bv*NHv*Sv*HDv];   // tf32 bits TRANSPOSED [B][H][HD][S]
__device__ float g_att[TOK*Dv];     // tf32 bits
__device__ float g_probs[TOK];
__device__ float g_wsel[TOK];
__device__ float g_g1[TOK*FFv];
__device__ float g_g2[TOK*FFv];

#define OFF_QKV  0
#define OFF_WO   1843200
#define OFF_GATE 2457600
#define OFF_UP   4116480
#define OFF_DOWN 5775360
#define TOTW     7434240
__device__ float g_wt[TOTW];

__device__ __forceinline__ float to_tf32(float x){
    unsigned u; asm("cvt.rna.tf32.f32 %0, %1;" : "=r"(u) : "f"(x));
    return __uint_as_float(u);
}
__device__ __forceinline__ unsigned fbits(float x){ return __float_as_uint(x); }

#define MMA_TF32(acc, A0,A1,A2,A3, B0,B1)                                   \
    asm volatile(                                                           \
        "mma.sync.aligned.m16n8k8.row.col.f32.tf32.tf32.f32 "               \
        "{%0,%1,%2,%3},{%4,%5,%6,%7},{%8,%9},{%0,%1,%2,%3};\n"              \
        : "+f"(acc[0]),"+f"(acc[1]),"+f"(acc[2]),"+f"(acc[3])               \
        : "r"(A0),"r"(A1),"r"(A2),"r"(A3),"r"(B0),"r"(B1))

// ---------------- conversions / embedding ----------------
__global__ void k_cvt(const float* __restrict__ in, float* __restrict__ out, int n){
    int i = blockIdx.x*256 + threadIdx.x;
    if (i < n) out[i] = to_tf32(in[i]);
}

__global__ void k_embed(const int* __restrict__ ids, const int* __restrict__ iter,
                        const float* __restrict__ emb, const float* __restrict__ iter_emb) {
    int idx = blockIdx.x*256 + threadIdx.x;
    if (idx >= TOK*Dv) return;
    int t = idx / Dv, d = idx - t*Dv;
    float v = emb[(size_t)ids[t]*Dv + d];
    int it = iter[0];
    if (it < NLOOPSv) v += iter_emb[it*Dv + d];
    g_x[idx] = v;
}

// ---------------- rmsnorm ----------------
__global__ void k_rmsnorm(const float* __restrict__ in, const float* __restrict__ w,
                          float* __restrict__ out, int tf32out) {
    int gw = (blockIdx.x*256 + threadIdx.x) >> 5;
    int lane = threadIdx.x & 31;
    if (gw >= TOK) return;
    const float* xr = in + (size_t)gw*Dv;
    float v[10]; float ss = 0.f;
    #pragma unroll
    for (int i=0;i<10;i++){ v[i] = xr[lane+32*i]; ss = fmaf(v[i],v[i],ss); }
    #pragma unroll
    for (int o=16;o;o>>=1) ss += __shfl_xor_sync(0xffffffffu, ss, o);
    float inv = rsqrtf(ss*(1.f/Dv) + 1e-6f);
    float* orow = out + (size_t)gw*Dv;
    #pragma unroll
    for (int i=0;i<10;i++){
        float val = w[lane+32*i]*v[i]*inv;
        orow[lane+32*i] = tf32out ? to_tf32(val) : val;
    }
}

// ---------------- tf32 tensor-core GEMM (same as R2) ----------------
#define CPA(dst, src) asm volatile("cp.async.cg.shared.global [%0], [%1], 16;\n" :: "r"(dst), "l"(src))
#define CPAZ(dst, src, sz) asm volatile("cp.async.cg.shared.global [%0], [%1], 16, %2;\n" :: "r"(dst), "l"(src), "r"(sz))

__global__ __launch_bounds__(256) void k_gemm_tc(
    const float* __restrict__ A, const float* __restrict__ W, float* __restrict__ C,
    const float* __restrict__ aux, const float* __restrict__ rowscale,
    int M, int N, int K, int ep)
{
    extern __shared__ float sm[];
    const int SA = 128*36;
    unsigned base = (unsigned)__cvta_generic_to_shared(sm);
    unsigned Asb[2] = { base, base + SA*4u };
    unsigned Wsb[2] = { base + 2u*SA*4u, base + 3u*SA*4u };
    float* Asp[2] = { sm, sm + SA };
    float* Wsp[2] = { sm + 2*SA, sm + 3*SA };

    int tid = threadIdx.x;
    int lane = tid & 31, warp = tid >> 5;
    int wm = warp >> 1, wn = warp & 1;
    int m0 = blockIdx.y*128, n0 = blockIdx.x*128;

    int lrow = tid >> 3;
    int c16  = tid & 7;
    const float* Ag = A + (size_t)(m0 + lrow)*K + c16*4;
    int wr0 = n0 + lrow;

    float acc[2][8][4];
    #pragma unroll
    for (int i=0;i<2;i++)
        #pragma unroll
        for (int j=0;j<8;j++)
            #pragma unroll
            for (int c=0;c<4;c++) acc[i][j][c]=0.f;

    int nkb = K >> 5;

    #define LOADTILE(buf, k0) do {                                              \
        _Pragma("unroll")                                                       \
        for (int i=0;i<4;i++){                                                  \
            int r = lrow + 32*i;                                                \
            unsigned d = Asb[buf] + (unsigned)((r*36 + c16*4)*4);               \
            CPA(d, Ag + (size_t)(32*i)*K + (k0));                               \
        }                                                                       \
        _Pragma("unroll")                                                       \
        for (int i=0;i<4;i++){                                                  \
            int r = lrow + 32*i;                                                \
            int wr = wr0 + 32*i;                                                \
            unsigned sz = (wr < N) ? 16u : 0u;                                  \
            const float* src = W + (size_t)(wr < N ? wr : 0)*K + (k0) + c16*4;  \
            unsigned d = Wsb[buf] + (unsigned)((r*36 + c16*4)*4);               \
            CPAZ(d, src, sz);                                                   \
        }                                                                       \
    } while(0)

    LOADTILE(0, 0);
    asm volatile("cp.async.commit_group;\n");

    int buf = 0;
    int lr = lane >> 2, lc = lane & 3;
    for (int kb=0; kb<nkb; kb++){
        if (kb+1 < nkb){
            LOADTILE(buf^1, (kb+1)*32);
            asm volatile("cp.async.commit_group;\n");
            asm volatile("cp.async.wait_group 1;\n");
        } else {
            asm volatile("cp.async.wait_group 0;\n");
        }
        __syncthreads();

        const float* Ab = Asp[buf];
        const float* Wb = Wsp[buf];
        #pragma unroll
        for (int ks=0; ks<4; ks++){
            unsigned a[2][4], b[8][2];
            #pragma unroll
            for (int mf=0; mf<2; mf++){
                const float* p = Ab + (wm*32 + mf*16 + lr)*36 + ks*8 + lc;
                a[mf][0] = fbits(p[0]);
                a[mf][1] = fbits(p[8*36]);
                a[mf][2] = fbits(p[4]);
                a[mf][3] = fbits(p[8*36+4]);
            }
            #pragma unroll
            for (int nf=0; nf<8; nf++){
                const float* p = Wb + (wn*64 + nf*8 + lr)*36 + ks*8 + lc;
                b[nf][0] = fbits(p[0]);
                b[nf][1] = fbits(p[4]);
            }
            #pragma unroll
            for (int mf=0; mf<2; mf++)
                #pragma unroll
                for (int nf=0; nf<8; nf++)
                    MMA_TF32(acc[mf][nf], a[mf][0],a[mf][1],a[mf][2],a[mf][3],
                             b[nf][0], b[nf][1]);
        }
        buf ^= 1;
        __syncthreads();
    }

    #pragma unroll
    for (int mf=0; mf<2; mf++){
        #pragma unroll
        for (int nf=0; nf<8; nf++){
            int mbase = m0 + wm*32 + mf*16 + lr;
            int nbase = n0 + wn*64 + nf*8 + lc*2;
            #pragma unroll
            for (int c=0;c<4;c++){
                int m = mbase + (c>=2 ? 8 : 0);
                int n = nbase + (c&1);
                if (n < N){
                    size_t o = (size_t)m*N + n;
                    float v = acc[mf][nf][c], r;
                    if (ep==0) r = v;
                    else if (ep==1) r = aux[o] + v;
                    else if (ep==2) r = aux[o] + rowscale[m]*v;
                    else { float g = aux[o]; r = to_tf32(g * v / (1.f + expf(-g))); }
                    C[o] = r;
                }
            }
        }
    }
}

// ---------------- RoPE (q,k only, tf32 out) ----------------
__global__ void k_rope() {
    int idx = blockIdx.x*256 + threadIdx.x;
    if (idx >= TOK*Dv) return;
    int t = idx / Dv;
    int rem = idx - t*Dv;
    int h = rem >> 6, d = rem & 63;
    int s = t & (Sv-1), b = t >> 11;
    const float* base = g_qkv + (size_t)t*(3*Dv) + h*HDv;
    float qv = base[d], kv = base[Dv + d];
    int i2 = d & 31;
    float freq = expf(-(float)(2*i2) * (9.210340371976184f/64.0f));
    float ang = (float)s * freq;
    float sn, cs; sincosf(ang, &sn, &cs);
    float qr, kr;
    if (d < 32) { qr = -base[d+32];      kr = -base[Dv+d+32]; }
    else        { qr =  base[d-32];      kr =  base[Dv+d-32]; }
    size_t o = (((size_t)b*NHv + h)*Sv + s)*HDv + d;
    g_q[o] = to_tf32(qv*cs + qr*sn);
    g_k[o] = to_tf32(kv*cs + kr*sn);
}

// ---------------- V transpose: g_qkv[...,2D..] -> g_v [B][H][HD][S], tf32 ----------------
__global__ __launch_bounds__(256) void k_vtr() {
    __shared__ float t[32][33];
    int st = blockIdx.x*32;
    int dh = blockIdx.y;
    int h = dh >> 1, dt = (dh & 1)*32;
    int b = blockIdx.z;
    int lx = threadIdx.x & 31, ly = threadIdx.x >> 5;   // 32 x 8
    const float* src = g_qkv + (size_t)(b*Sv)*(3*Dv) + 2*Dv + h*HDv + dt + lx;
    #pragma unroll
    for (int r=0;r<4;r++){
        int s = st + ly + r*8;
        t[ly+r*8][lx] = src[(size_t)s*(3*Dv)];
    }
    __syncthreads();
    float* dst = g_v + (((size_t)b*NHv + h)*HDv)*Sv + st + lx;
    #pragma unroll
    for (int r=0;r<4;r++){
        int d = dt + ly + r*8;
        dst[(size_t)d*Sv] = to_tf32(t[lx][ly+r*8]);
    }
}

// ---------------- tf32 tensor-core flash attention ----------------
// 64 q rows / CTA, 4 warps x 16 rows, HD=64, key tiles of 64.
#define APAD 68
__global__ __launch_bounds__(128) void k_attn_tc() {
    extern __shared__ float sm[];
    float* Qs = sm;                  // [64][68]
    float* Ks = sm + 64*APAD;
    float* Vt = sm + 2*64*APAD;      // [dim][key]
    float* Ps = sm + 3*64*APAD;
    int qt = blockIdx.x, h = blockIdx.y, b = blockIdx.z;
    int tid = threadIdx.x, lane = tid & 31, warp = tid >> 5;
    int lr = lane >> 2, lc = lane & 3;
    const size_t headoff = ((size_t)b*NHv + h)*(size_t)Sv*HDv;
    const float* Qg = g_q + headoff + (size_t)qt*64*HDv;
    const float* Kg0 = g_k + headoff;
    const float* Vg0 = g_v + headoff;   // [HD][S]

    #pragma unroll
    for (int i=0;i<8;i++){
        int idx = (tid + i*128)*4;
        int row = idx >> 6, col = idx & 63;
        *(float4*)(Qs + row*APAD + col) = *(const float4*)(Qg + idx);
    }

    float o[8][4];
    #pragma unroll
    for (int nt=0;nt<8;nt++)
        #pragma unroll
        for (int c=0;c<4;c++) o[nt][c]=0.f;
    float mr0=-1e30f, mr1=-1e30f, ls0=0.f, ls1=0.f;
    int qrow = qt*64 + warp*16 + lr;

    for (int t0=0; t0<=qt; t0++){
        __syncthreads();
        const float* Kg = Kg0 + (size_t)t0*64*HDv;
        #pragma unroll
        for (int i=0;i<8;i++){
            int idx = (tid + i*128)*4;
            int row = idx >> 6, col = idx & 63;
            *(float4*)(Ks + row*APAD + col) = *(const float4*)(Kg + idx);
            *(float4*)(Vt + row*APAD + col) = *(const float4*)(Vg0 + (size_t)row*Sv + t0*64 + col);
        }
        __syncthreads();

        // S = Q K^T
        float sacc[8][4];
        #pragma unroll
        for (int nt=0;nt<8;nt++)
            #pragma unroll
            for (int c=0;c<4;c++) sacc[nt][c]=0.f;
        #pragma unroll
        for (int ks=0; ks<8; ks++){
            const float* ap = Qs + (warp*16 + lr)*APAD + ks*8 + lc;
            unsigned a0=fbits(ap[0]), a1=fbits(ap[8*APAD]),
                     a2=fbits(ap[4]), a3=fbits(ap[8*APAD+4]);
            #pragma unroll
            for (int nt=0; nt<8; nt++){
                const float* bp = Ks + (nt*8 + lr)*APAD + ks*8 + lc;
                MMA_TF32(sacc[nt], a0,a1,a2,a3, fbits(bp[0]), fbits(bp[4]));
            }
        }

        // scale + causal mask + tile row max
        bool diag = (t0 == qt);
        float mt0=-1e30f, mt1=-1e30f;
        #pragma unroll
        for (int nt=0;nt<8;nt++){
            #pragma unroll
            for (int c=0;c<4;c++){
                float s = sacc[nt][c]*0.125f;
                if (diag){
                    int col = t0*64 + nt*8 + lc*2 + (c&1);
                    int row = qrow + ((c>=2)?8:0);
                    if (col > row) s = -1e30f;
                }
                sacc[nt][c] = s;
                if (c>=2) mt1 = fmaxf(mt1, s); else mt0 = fmaxf(mt0, s);
            }
        }
        mt0 = fmaxf(mt0, __shfl_xor_sync(0xffffffffu, mt0, 1));
        mt0 = fmaxf(mt0, __shfl_xor_sync(0xffffffffu, mt0, 2));
        mt1 = fmaxf(mt1, __shfl_xor_sync(0xffffffffu, mt1, 1));
        mt1 = fmaxf(mt1, __shfl_xor_sync(0xffffffffu, mt1, 2));
        float mn0 = fmaxf(mr0, mt0), mn1 = fmaxf(mr1, mt1);
        float sc0 = __expf(mr0 - mn0), sc1 = __expf(mr1 - mn1);
        ls0 *= sc0; ls1 *= sc1;
        #pragma unroll
        for (int nt=0;nt<8;nt++){
            o[nt][0]*=sc0; o[nt][1]*=sc0; o[nt][2]*=sc1; o[nt][3]*=sc1;
        }
        mr0 = mn0; mr1 = mn1;

        // exp + store P (tf32)
        float* pr0 = Ps + (warp*16 + lr)*APAD;
        float* pr1 = pr0 + 8*APAD;
        #pragma unroll
        for (int nt=0;nt<8;nt++){
            int col = nt*8 + lc*2;
            float p0 = __expf(sacc[nt][0] - mn0);
            float p1 = __expf(sacc[nt][1] - mn0);
            float p2 = __expf(sacc[nt][2] - mn1);
            float p3 = __expf(sacc[nt][3] - mn1);
            ls0 += p0 + p1; ls1 += p2 + p3;
            pr0[col]   = to_tf32(p0);
            pr0[col+1] = to_tf32(p1);
            pr1[col]   = to_tf32(p2);
            pr1[col+1] = to_tf32(p3);
        }
        __syncwarp();

        // O += P V  (B = Vt[dim][key])
        #pragma unroll
        for (int ks=0; ks<8; ks++){
            const float* ap = Ps + (warp*16 + lr)*APAD + ks*8 + lc;
            unsigned a0=fbits(ap[0]), a1=fbits(ap[8*APAD]),
                     a2=fbits(ap[4]), a3=fbits(ap[8*APAD+4]);
            #pragma unroll
            for (int nt=0; nt<8; nt++){
                const float* bp = Vt + (nt*8 + lr)*APAD + ks*8 + lc;
                MMA_TF32(o[nt], a0,a1,a2,a3, fbits(bp[0]), fbits(bp[4]));
            }
        }
    }

    ls0 += __shfl_xor_sync(0xffffffffu, ls0, 1);
    ls0 += __shfl_xor_sync(0xffffffffu, ls0, 2);
    ls1 += __shfl_xor_sync(0xffffffffu, ls1, 1);
    ls1 += __shfl_xor_sync(0xffffffffu, ls1, 2);
    float inv0 = 1.f/ls0, inv1 = 1.f/ls1;
    int tok0 = b*Sv + qt*64 + warp*16 + lr;
    float* out0 = g_att + (size_t)tok0*Dv + h*HDv;
    float* out1 = out0 + 8*(size_t)Dv;
    #pragma unroll
    for (int nt=0;nt<8;nt++){
        int col = nt*8 + lc*2;
        out0[col]   = to_tf32(o[nt][0]*inv0);
        out0[col+1] = to_tf32(o[nt][1]*inv0);
        out1[col]   = to_tf32(o[nt][2]*inv1);
        out1[col+1] = to_tf32(o[nt][3]*inv1);
    }
}

// ---------------- router ----------------
__global__ void k_router(const float* __restrict__ rw) {
    int gw = (blockIdx.x*256 + threadIdx.x) >> 5;
    int lane = threadIdx.x & 31;
    if (gw >= TOK) return;
    const float* xr = g_x + (size_t)gw*Dv;
    float s = 0.f;
    #pragma unroll
    for (int i=0;i<10;i++) s = fmaf(xr[lane+32*i], rw[lane+32*i], s);
    #pragma unroll
    for (int o=16;o;o>>=1) s += __shfl_xor_sync(0xffffffffu, s, o);
    if (lane==0) g_probs[gw] = 1.f/(1.f+expf(-s));
}

// ---------------- exact top-k by rank counting ----------------
__global__ __launch_bounds__(256) void k_topk() {
    __shared__ float p[Sv];
    int b = blockIdx.x, part = blockIdx.y;
    int tid = threadIdx.x;
    for (int i=tid;i<Sv;i+=256) p[i] = g_probs[b*Sv+i];
    __syncthreads();
    int i = part*256 + tid;
    float pi = p[i];
    int cnt = 0;
    #pragma unroll 8
    for (int j=0;j<Sv;j++) {
        float pj = p[j];
        cnt += (pj > pi) || (pj == pi && j < i);
    }
    g_wsel[b*Sv+i] = (cnt < KSEL) ? pi : 0.f;
}

// ---------------- driver ----------------
extern "C" void kernel_launch(void* const* d_in, const int* in_sizes, int n_in,
                              void* d_out, int out_size) {
    const int*   ids        = (const int*)d_in[0];
    const int*   iter       = (const int*)d_in[1];
    const float* emb        = (const float*)d_in[2];
    const float* iter_emb   = (const float*)d_in[3];
    const float* attn_norm  = (const float*)d_in[4];
    const float* Wqkv       = (const float*)d_in[5];
    const float* wo         = (const float*)d_in[6];
    const float* router     = (const float*)d_in[7];
    const float* mlp_norm   = (const float*)d_in[8];
    const float* gatew      = (const float*)d_in[9];
    const float* upw        = (const float*)d_in[10];
    const float* downw      = (const float*)d_in[11];
    const float* final_norm = (const float*)d_in[12];
    float* out = (float*)d_out;

    float *xp,*hp,*qkvp,*attp,*g1p,*g2p,*wselp,*wtp;
    cudaGetSymbolAddress((void**)&xp,   g_x);
    cudaGetSymbolAddress((void**)&hp,   g_h);
    cudaGetSymbolAddress((void**)&qkvp, g_qkv);
    cudaGetSymbolAddress((void**)&attp, g_att);
    cudaGetSymbolAddress((void**)&g1p,  g_g1);
    cudaGetSymbolAddress((void**)&g2p,  g_g2);
    cudaGetSymbolAddress((void**)&wselp,g_wsel);
    cudaGetSymbolAddress((void**)&wtp,  g_wt);

    cudaFuncSetAttribute(k_attn_tc, cudaFuncAttributeMaxDynamicSharedMemorySize, 4*64*APAD*4);
    cudaFuncSetAttribute(k_gemm_tc, cudaFuncAttributeMaxDynamicSharedMemorySize, 73728);

    k_cvt<<<(1843200+255)/256,256>>>(Wqkv,  wtp+OFF_QKV,  1843200);
    k_cvt<<<(614400+255)/256, 256>>>(wo,    wtp+OFF_WO,   614400);
    k_cvt<<<(1658880+255)/256,256>>>(gatew, wtp+OFF_GATE, 1658880);
    k_cvt<<<(1658880+255)/256,256>>>(upw,   wtp+OFF_UP,   1658880);
    k_cvt<<<(1658880+255)/256,256>>>(downw, wtp+OFF_DOWN, 1658880);

    k_embed<<<(TOK*Dv+255)/256, 256>>>(ids, iter, emb, iter_emb);

    dim3 gq((3*Dv+127)/128, TOK/128);
    dim3 g320((Dv+127)/128, TOK/128);
    dim3 gff((FFv+127)/128, TOK/128);
    const int SMEMG = 73728;
    const int SMEMA = 4*64*APAD*4;

    for (int l=0;l<NLv;l++) {
        k_rmsnorm<<<TOK/8, 256>>>(xp, attn_norm + (size_t)l*Dv, hp, 1);
        k_gemm_tc<<<gq, 256, SMEMG>>>(hp, wtp+OFF_QKV + (size_t)l*960*320, qkvp,
                                      nullptr, nullptr, TOK, 3*Dv, Dv, 0);
        k_rope<<<(TOK*Dv+255)/256, 256>>>();
        k_vtr<<<dim3(Sv/32, 2*NHv, Bv), 256>>>();
        k_attn_tc<<<dim3(Sv/64, NHv, Bv), 128, SMEMA>>>();
        k_gemm_tc<<<g320, 256, SMEMG>>>(attp, wtp+OFF_WO + (size_t)l*320*320, xp,
                                        xp, nullptr, TOK, Dv, Dv, 1);
        k_router<<<TOK/8, 256>>>(router + (size_t)l*Dv);
        k_topk<<<dim3(Bv, Sv/256), 256>>>();
        k_rmsnorm<<<TOK/8, 256>>>(xp, mlp_norm + (size_t)l*Dv, hp, 1);
        k_gemm_tc<<<gff, 256, SMEMG>>>(hp, wtp+OFF_GATE + (size_t)l*FFv*320, g1p,
                                       nullptr, nullptr, TOK, FFv, Dv, 0);
        k_gemm_tc<<<gff, 256, SMEMG>>>(hp, wtp+OFF_UP + (size_t)l*FFv*320, g2p,
                                       g1p, nullptr, TOK, FFv, Dv, 3);
        k_gemm_tc<<<g320, 256, SMEMG>>>(g2p, wtp+OFF_DOWN + (size_t)l*320*FFv, xp,
                                        xp, wselp, TOK, Dv, FFv, 2);
    }
    k_rmsnorm<<<TOK/8, 256>>>(xp, final_norm, out, 0);
}

// round 4
// speedup vs baseline: 3.5782x; 1.0610x over previous
#include <cuda_runtime.h>
#include <cuda_bf16.h>
#include <math.h>

#define Bv 8
#define Sv 2048
#define Dv 320
#define NHv 5
#define HDv 64
#define FFv 864
#define NLv 6
#define NLOOPSv 8
#define TOK (Bv*Sv)
#define KSEL 1638
#define MPAD 1664
#define MSEL (Bv*MPAD)   // 13312

// ---------------- scratch ----------------
__device__ float g_x[TOK*Dv];
__device__ float g_h[TOK*Dv];       // tf32 bits
__device__ float g_qkv[TOK*3*Dv];
__device__ float g_q[Bv*NHv*Sv*HDv];   // tf32 [B][H][S][HD]
__device__ float g_k[Bv*NHv*Sv*HDv];   // tf32 [B][H][S][HD]
__device__ float g_v[Bv*NHv*Sv*HDv];   // tf32 TRANSPOSED [B][H][HD][S]
__device__ float g_att[TOK*Dv];     // tf32 bits
__device__ float g_probs[TOK];
__device__ int   g_sel[MSEL];
__device__ float g_wselc[MSEL];
__device__ float g_g1[TOK*FFv];
__device__ float g_g2[TOK*FFv];

#define OFF_QKV  0
#define OFF_WO   1843200
#define OFF_GATE 2457600
#define OFF_UP   4116480
#define OFF_DOWN 5775360
#define TOTW     7434240
__device__ float g_wt[TOTW];

__device__ __forceinline__ float to_tf32(float x){
    unsigned u; asm("cvt.rna.tf32.f32 %0, %1;" : "=r"(u) : "f"(x));
    return __uint_as_float(u);
}
__device__ __forceinline__ unsigned fbits(float x){ return __float_as_uint(x); }

#define MMA_TF32(acc, A0,A1,A2,A3, B0,B1)                                   \
    asm volatile(                                                           \
        "mma.sync.aligned.m16n8k8.row.col.f32.tf32.tf32.f32 "               \
        "{%0,%1,%2,%3},{%4,%5,%6,%7},{%8,%9},{%0,%1,%2,%3};\n"              \
        : "+f"(acc[0]),"+f"(acc[1]),"+f"(acc[2]),"+f"(acc[3])               \
        : "r"(A0),"r"(A1),"r"(A2),"r"(A3),"r"(B0),"r"(B1))

// ---------------- conversions / embedding ----------------
__global__ void k_cvt(const float* __restrict__ in, float* __restrict__ out, int n){
    int i = blockIdx.x*256 + threadIdx.x;
    if (i < n) out[i] = to_tf32(in[i]);
}

__global__ void k_embed(const int* __restrict__ ids, const int* __restrict__ iter,
                        const float* __restrict__ emb, const float* __restrict__ iter_emb) {
    int idx = blockIdx.x*256 + threadIdx.x;
    if (idx >= TOK*Dv) return;
    int t = idx / Dv, d = idx - t*Dv;
    float v = emb[(size_t)ids[t]*Dv + d];
    int it = iter[0];
    if (it < NLOOPSv) v += iter_emb[it*Dv + d];
    g_x[idx] = v;
}

__global__ void k_clearpad(){
    int i = threadIdx.x;
    if (i < Bv*(MPAD-KSEL)){
        int b = i/(MPAD-KSEL), j = i%(MPAD-KSEL);
        g_sel[b*MPAD + KSEL + j] = -1;
        g_wselc[b*MPAD + KSEL + j] = 0.f;
    }
}

// ---------------- rmsnorm (dense) ----------------
__global__ void k_rmsnorm(const float* __restrict__ in, const float* __restrict__ w,
                          float* __restrict__ out, int tf32out) {
    int gw = (blockIdx.x*256 + threadIdx.x) >> 5;
    int lane = threadIdx.x & 31;
    if (gw >= TOK) return;
    const float* xr = in + (size_t)gw*Dv;
    float v[10]; float ss = 0.f;
    #pragma unroll
    for (int i=0;i<10;i++){ v[i] = xr[lane+32*i]; ss = fmaf(v[i],v[i],ss); }
    #pragma unroll
    for (int o=16;o;o>>=1) ss += __shfl_xor_sync(0xffffffffu, ss, o);
    float inv = rsqrtf(ss*(1.f/Dv) + 1e-6f);
    float* orow = out + (size_t)gw*Dv;
    #pragma unroll
    for (int i=0;i<10;i++){
        float val = w[lane+32*i]*v[i]*inv;
        orow[lane+32*i] = tf32out ? to_tf32(val) : val;
    }
}

// ---------------- rmsnorm over selected (compact) rows ----------------
__global__ void k_rmsnorm_sel(const float* __restrict__ w) {
    int gw = (blockIdx.x*256 + threadIdx.x) >> 5;
    int lane = threadIdx.x & 31;
    if (gw >= MSEL) return;
    int tok = g_sel[gw];
    float* orow = g_h + (size_t)gw*Dv;
    if (tok < 0){
        #pragma unroll
        for (int i=0;i<10;i++) orow[lane+32*i] = 0.f;
        return;
    }
    const float* xr = g_x + (size_t)tok*Dv;
    float v[10]; float ss = 0.f;
    #pragma unroll
    for (int i=0;i<10;i++){ v[i] = xr[lane+32*i]; ss = fmaf(v[i],v[i],ss); }
    #pragma unroll
    for (int o=16;o;o>>=1) ss += __shfl_xor_sync(0xffffffffu, ss, o);
    float inv = rsqrtf(ss*(1.f/Dv) + 1e-6f);
    #pragma unroll
    for (int i=0;i<10;i++)
        orow[lane+32*i] = to_tf32(w[lane+32*i]*v[i]*inv);
}

// ---------------- tf32 tensor-core GEMM ----------------
#define CPA(dst, src) asm volatile("cp.async.cg.shared.global [%0], [%1], 16;\n" :: "r"(dst), "l"(src))
#define CPAZ(dst, src, sz) asm volatile("cp.async.cg.shared.global [%0], [%1], 16, %2;\n" :: "r"(dst), "l"(src), "r"(sz))

__global__ __launch_bounds__(256) void k_gemm_tc(
    const float* __restrict__ A, const float* __restrict__ W, float* __restrict__ C,
    const float* __restrict__ aux, const float* __restrict__ rowscale,
    const int* __restrict__ sel,
    int M, int N, int K, int ep)
{
    extern __shared__ float sm[];
    const int SA = 128*36;
    unsigned base = (unsigned)__cvta_generic_to_shared(sm);
    unsigned Asb[2] = { base, base + SA*4u };
    unsigned Wsb[2] = { base + 2u*SA*4u, base + 3u*SA*4u };
    float* Asp[2] = { sm, sm + SA };
    float* Wsp[2] = { sm + 2*SA, sm + 3*SA };

    int tid = threadIdx.x;
    int lane = tid & 31, warp = tid >> 5;
    int wm = warp >> 1, wn = warp & 1;
    int m0 = blockIdx.y*128, n0 = blockIdx.x*128;

    int lrow = tid >> 3;
    int c16  = tid & 7;
    const float* Ag = A + (size_t)(m0 + lrow)*K + c16*4;
    int wr0 = n0 + lrow;

    float acc[2][8][4];
    #pragma unroll
    for (int i=0;i<2;i++)
        #pragma unroll
        for (int j=0;j<8;j++)
            #pragma unroll
            for (int c=0;c<4;c++) acc[i][j][c]=0.f;

    int nkb = K >> 5;

    #define LOADTILE(buf, k0) do {                                              \
        _Pragma("unroll")                                                       \
        for (int i=0;i<4;i++){                                                  \
            int r = lrow + 32*i;                                                \
            unsigned d = Asb[buf] + (unsigned)((r*36 + c16*4)*4);               \
            CPA(d, Ag + (size_t)(32*i)*K + (k0));                               \
        }                                                                       \
        _Pragma("unroll")                                                       \
        for (int i=0;i<4;i++){                                                  \
            int r = lrow + 32*i;                                                \
            int wr = wr0 + 32*i;                                                \
            unsigned sz = (wr < N) ? 16u : 0u;                                  \
            const float* src = W + (size_t)(wr < N ? wr : 0)*K + (k0) + c16*4;  \
            unsigned d = Wsb[buf] + (unsigned)((r*36 + c16*4)*4);               \
            CPAZ(d, src, sz);                                                   \
        }                                                                       \
    } while(0)

    LOADTILE(0, 0);
    asm volatile("cp.async.commit_group;\n");

    int buf = 0;
    int lr = lane >> 2, lc = lane & 3;
    for (int kb=0; kb<nkb; kb++){
        if (kb+1 < nkb){
            LOADTILE(buf^1, (kb+1)*32);
            asm volatile("cp.async.commit_group;\n");
            asm volatile("cp.async.wait_group 1;\n");
        } else {
            asm volatile("cp.async.wait_group 0;\n");
        }
        __syncthreads();

        const float* Ab = Asp[buf];
        const float* Wb = Wsp[buf];
        #pragma unroll
        for (int ks=0; ks<4; ks++){
            unsigned a[2][4], b[8][2];
            #pragma unroll
            for (int mf=0; mf<2; mf++){
                const float* p = Ab + (wm*32 + mf*16 + lr)*36 + ks*8 + lc;
                a[mf][0] = fbits(p[0]);
                a[mf][1] = fbits(p[8*36]);
                a[mf][2] = fbits(p[4]);
                a[mf][3] = fbits(p[8*36+4]);
            }
            #pragma unroll
            for (int nf=0; nf<8; nf++){
                const float* p = Wb + (wn*64 + nf*8 + lr)*36 + ks*8 + lc;
                b[nf][0] = fbits(p[0]);
                b[nf][1] = fbits(p[4]);
            }
            #pragma unroll
            for (int mf=0; mf<2; mf++)
                #pragma unroll
                for (int nf=0; nf<8; nf++)
                    MMA_TF32(acc[mf][nf], a[mf][0],a[mf][1],a[mf][2],a[mf][3],
                             b[nf][0], b[nf][1]);
        }
        buf ^= 1;
        __syncthreads();
    }

    #pragma unroll
    for (int mf=0; mf<2; mf++){
        #pragma unroll
        for (int nf=0; nf<8; nf++){
            int mbase = m0 + wm*32 + mf*16 + lr;
            int nbase = n0 + wn*64 + nf*8 + lc*2;
            #pragma unroll
            for (int c=0;c<4;c++){
                int m = mbase + (c>=2 ? 8 : 0);
                int n = nbase + (c&1);
                if (n < N){
                    float v = acc[mf][nf][c];
                    if (ep==2){
                        int tok = sel[m];
                        if (tok >= 0){
                            size_t o = (size_t)tok*N + n;
                            C[o] = aux[o] + rowscale[m]*v;
                        }
                    } else {
                        size_t o = (size_t)m*N + n;
                        if (ep==0) C[o] = v;
                        else if (ep==1) C[o] = aux[o] + v;
                        else { float g = aux[o]; C[o] = to_tf32(g * v / (1.f + expf(-g))); }
                    }
                }
            }
        }
    }
}

// ---------------- RoPE (q,k only, tf32 out) ----------------
__global__ void k_rope() {
    int idx = blockIdx.x*256 + threadIdx.x;
    if (idx >= TOK*Dv) return;
    int t = idx / Dv;
    int rem = idx - t*Dv;
    int h = rem >> 6, d = rem & 63;
    int s = t & (Sv-1), b = t >> 11;
    const float* base = g_qkv + (size_t)t*(3*Dv) + h*HDv;
    float qv = base[d], kv = base[Dv + d];
    int i2 = d & 31;
    float freq = expf(-(float)(2*i2) * (9.210340371976184f/64.0f));
    float ang = (float)s * freq;
    float sn, cs; sincosf(ang, &sn, &cs);
    float qr, kr;
    if (d < 32) { qr = -base[d+32];      kr = -base[Dv+d+32]; }
    else        { qr =  base[d-32];      kr =  base[Dv+d-32]; }
    size_t o = (((size_t)b*NHv + h)*Sv + s)*HDv + d;
    g_q[o] = to_tf32(qv*cs + qr*sn);
    g_k[o] = to_tf32(kv*cs + kr*sn);
}

// ---------------- V transpose -> [B][H][HD][S], tf32 ----------------
__global__ __launch_bounds__(256) void k_vtr() {
    __shared__ float t[32][33];
    int st = blockIdx.x*32;
    int dh = blockIdx.y;
    int h = dh >> 1, dt = (dh & 1)*32;
    int b = blockIdx.z;
    int lx = threadIdx.x & 31, ly = threadIdx.x >> 5;
    const float* src = g_qkv + (size_t)(b*Sv)*(3*Dv) + 2*Dv + h*HDv + dt + lx;
    #pragma unroll
    for (int r=0;r<4;r++){
        int s = st + ly + r*8;
        t[ly+r*8][lx] = src[(size_t)s*(3*Dv)];
    }
    __syncthreads();
    float* dst = g_v + (((size_t)b*NHv + h)*HDv)*Sv + st + lx;
    #pragma unroll
    for (int r=0;r<4;r++){
        int d = dt + ly + r*8;
        dst[(size_t)d*Sv] = to_tf32(t[lx][ly+r*8]);
    }
}

// ---------------- tf32 tensor-core flash attention ----------------
#define APAD 68
__global__ __launch_bounds__(128) void k_attn_tc() {
    extern __shared__ float sm[];
    float* Qs = sm;
    float* Ks = sm + 64*APAD;
    float* Vt = sm + 2*64*APAD;
    float* Ps = sm + 3*64*APAD;
    int qt = gridDim.x - 1 - blockIdx.x;   // heavy tiles first
    int h = blockIdx.y, b = blockIdx.z;
    int tid = threadIdx.x, lane = tid & 31, warp = tid >> 5;
    int lr = lane >> 2, lc = lane & 3;
    const size_t headoff = ((size_t)b*NHv + h)*(size_t)Sv*HDv;
    const float* Qg = g_q + headoff + (size_t)qt*64*HDv;
    const float* Kg0 = g_k + headoff;
    const float* Vg0 = g_v + headoff;

    #pragma unroll
    for (int i=0;i<8;i++){
        int idx = (tid + i*128)*4;
        int row = idx >> 6, col = idx & 63;
        *(float4*)(Qs + row*APAD + col) = *(const float4*)(Qg + idx);
    }

    float o[8][4];
    #pragma unroll
    for (int nt=0;nt<8;nt++)
        #pragma unroll
        for (int c=0;c<4;c++) o[nt][c]=0.f;
    float mr0=-1e30f, mr1=-1e30f, ls0=0.f, ls1=0.f;
    int qrow = qt*64 + warp*16 + lr;

    for (int t0=0; t0<=qt; t0++){
        __syncthreads();
        const float* Kg = Kg0 + (size_t)t0*64*HDv;
        #pragma unroll
        for (int i=0;i<8;i++){
            int idx = (tid + i*128)*4;
            int row = idx >> 6, col = idx & 63;
            *(float4*)(Ks + row*APAD + col) = *(const float4*)(Kg + idx);
            *(float4*)(Vt + row*APAD + col) = *(const float4*)(Vg0 + (size_t)row*Sv + t0*64 + col);
        }
        __syncthreads();

        float sacc[8][4];
        #pragma unroll
        for (int nt=0;nt<8;nt++)
            #pragma unroll
            for (int c=0;c<4;c++) sacc[nt][c]=0.f;
        #pragma unroll
        for (int ks=0; ks<8; ks++){
            const float* ap = Qs + (warp*16 + lr)*APAD + ks*8 + lc;
            unsigned a0=fbits(ap[0]), a1=fbits(ap[8*APAD]),
                     a2=fbits(ap[4]), a3=fbits(ap[8*APAD+4]);
            #pragma unroll
            for (int nt=0; nt<8; nt++){
                const float* bp = Ks + (nt*8 + lr)*APAD + ks*8 + lc;
                MMA_TF32(sacc[nt], a0,a1,a2,a3, fbits(bp[0]), fbits(bp[4]));
            }
        }

        bool diag = (t0 == qt);
        float mt0=-1e30f, mt1=-1e30f;
        #pragma unroll
        for (int nt=0;nt<8;nt++){
            #pragma unroll
            for (int c=0;c<4;c++){
                float s = sacc[nt][c]*0.125f;
                if (diag){
                    int col = t0*64 + nt*8 + lc*2 + (c&1);
                    int row = qrow + ((c>=2)?8:0);
                    if (col > row) s = -1e30f;
                }
                sacc[nt][c] = s;
                if (c>=2) mt1 = fmaxf(mt1, s); else mt0 = fmaxf(mt0, s);
            }
        }
        mt0 = fmaxf(mt0, __shfl_xor_sync(0xffffffffu, mt0, 1));
        mt0 = fmaxf(mt0, __shfl_xor_sync(0xffffffffu, mt0, 2));
        mt1 = fmaxf(mt1, __shfl_xor_sync(0xffffffffu, mt1, 1));
        mt1 = fmaxf(mt1, __shfl_xor_sync(0xffffffffu, mt1, 2));
        float mn0 = fmaxf(mr0, mt0), mn1 = fmaxf(mr1, mt1);
        float sc0 = __expf(mr0 - mn0), sc1 = __expf(mr1 - mn1);
        ls0 *= sc0; ls1 *= sc1;
        #pragma unroll
        for (int nt=0;nt<8;nt++){
            o[nt][0]*=sc0; o[nt][1]*=sc0; o[nt][2]*=sc1; o[nt][3]*=sc1;
        }
        mr0 = mn0; mr1 = mn1;

        float* pr0 = Ps + (warp*16 + lr)*APAD;
        float* pr1 = pr0 + 8*APAD;
        #pragma unroll
        for (int nt=0;nt<8;nt++){
            int col = nt*8 + lc*2;
            float p0 = __expf(sacc[nt][0] - mn0);
            float p1 = __expf(sacc[nt][1] - mn0);
            float p2 = __expf(sacc[nt][2] - mn1);
            float p3 = __expf(sacc[nt][3] - mn1);
            ls0 += p0 + p1; ls1 += p2 + p3;
            pr0[col]   = to_tf32(p0);
            pr0[col+1] = to_tf32(p1);
            pr1[col]   = to_tf32(p2);
            pr1[col+1] = to_tf32(p3);
        }
        __syncwarp();

        #pragma unroll
        for (int ks=0; ks<8; ks++){
            const float* ap = Ps + (warp*16 + lr)*APAD + ks*8 + lc;
            unsigned a0=fbits(ap[0]), a1=fbits(ap[8*APAD]),
                     a2=fbits(ap[4]), a3=fbits(ap[8*APAD+4]);
            #pragma unroll
            for (int nt=0; nt<8; nt++){
                const float* bp = Vt + (nt*8 + lr)*APAD + ks*8 + lc;
                MMA_TF32(o[nt], a0,a1,a2,a3, fbits(bp[0]), fbits(bp[4]));
            }
        }
    }

    ls0 += __shfl_xor_sync(0xffffffffu, ls0, 1);
    ls0 += __shfl_xor_sync(0xffffffffu, ls0, 2);
    ls1 += __shfl_xor_sync(0xffffffffu, ls1, 1);
    ls1 += __shfl_xor_sync(0xffffffffu, ls1, 2);
    float inv0 = 1.f/ls0, inv1 = 1.f/ls1;
    int tok0 = b*Sv + qt*64 + warp*16 + lr;
    float* out0 = g_att + (size_t)tok0*Dv + h*HDv;
    float* out1 = out0 + 8*(size_t)Dv;
    #pragma unroll
    for (int nt=0;nt<8;nt++){
        int col = nt*8 + lc*2;
        out0[col]   = to_tf32(o[nt][0]*inv0);
        out0[col+1] = to_tf32(o[nt][1]*inv0);
        out1[col]   = to_tf32(o[nt][2]*inv1);
        out1[col+1] = to_tf32(o[nt][3]*inv1);
    }
}

// ---------------- router ----------------
__global__ void k_router(const float* __restrict__ rw) {
    int gw = (blockIdx.x*256 + threadIdx.x) >> 5;
    int lane = threadIdx.x & 31;
    if (gw >= TOK) return;
    const float* xr = g_x + (size_t)gw*Dv;
    float s = 0.f;
    #pragma unroll
    for (int i=0;i<10;i++) s = fmaf(xr[lane+32*i], rw[lane+32*i], s);
    #pragma unroll
    for (int o=16;o;o>>=1) s += __shfl_xor_sync(0xffffffffu, s, o);
    if (lane==0) g_probs[gw] = 1.f/(1.f+expf(-s));
}

// ---------------- exact top-k -> compact selection ----------------
__global__ __launch_bounds__(256) void k_topk() {
    __shared__ float p[Sv];
    int b = blockIdx.x, part = blockIdx.y;
    int tid = threadIdx.x;
    for (int i=tid;i<Sv;i+=256) p[i] = g_probs[b*Sv+i];
    __syncthreads();
    int i = part*256 + tid;
    float pi = p[i];
    int cnt = 0;
    #pragma unroll 8
    for (int j=0;j<Sv;j++) {
        float pj = p[j];
        cnt += (pj > pi) || (pj == pi && j < i);
    }
    if (cnt < KSEL){
        g_sel[b*MPAD + cnt] = b*Sv + i;
        g_wselc[b*MPAD + cnt] = pi;
    }
}

// ---------------- driver ----------------
extern "C" void kernel_launch(void* const* d_in, const int* in_sizes, int n_in,
                              void* d_out, int out_size) {
    const int*   ids        = (const int*)d_in[0];
    const int*   iter       = (const int*)d_in[1];
    const float* emb        = (const float*)d_in[2];
    const float* iter_emb   = (const float*)d_in[3];
    const float* attn_norm  = (const float*)d_in[4];
    const float* Wqkv       = (const float*)d_in[5];
    const float* wo         = (const float*)d_in[6];
    const float* router     = (const float*)d_in[7];
    const float* mlp_norm   = (const float*)d_in[8];
    const float* gatew      = (const float*)d_in[9];
    const float* upw        = (const float*)d_in[10];
    const float* downw      = (const float*)d_in[11];
    const float* final_norm = (const float*)d_in[12];
    float* out = (float*)d_out;

    float *xp,*hp,*qkvp,*attp,*g1p,*g2p,*wselp,*wtp;
    int *selp;
    cudaGetSymbolAddress((void**)&xp,   g_x);
    cudaGetSymbolAddress((void**)&hp,   g_h);
    cudaGetSymbolAddress((void**)&qkvp, g_qkv);
    cudaGetSymbolAddress((void**)&attp, g_att);
    cudaGetSymbolAddress((void**)&g1p,  g_g1);
    cudaGetSymbolAddress((void**)&g2p,  g_g2);
    cudaGetSymbolAddress((void**)&wselp,g_wselc);
    cudaGetSymbolAddress((void**)&selp, g_sel);
    cudaGetSymbolAddress((void**)&wtp,  g_wt);

    cudaFuncSetAttribute(k_attn_tc, cudaFuncAttributeMaxDynamicSharedMemorySize, 4*64*APAD*4);
    cudaFuncSetAttribute(k_gemm_tc, cudaFuncAttributeMaxDynamicSharedMemorySize, 73728);

    k_cvt<<<(1843200+255)/256,256>>>(Wqkv,  wtp+OFF_QKV,  1843200);
    k_cvt<<<(614400+255)/256, 256>>>(wo,    wtp+OFF_WO,   614400);
    k_cvt<<<(1658880+255)/256,256>>>(gatew, wtp+OFF_GATE, 1658880);
    k_cvt<<<(1658880+255)/256,256>>>(upw,   wtp+OFF_UP,   1658880);
    k_cvt<<<(1658880+255)/256,256>>>(downw, wtp+OFF_DOWN, 1658880);

    k_embed<<<(TOK*Dv+255)/256, 256>>>(ids, iter, emb, iter_emb);
    k_clearpad<<<1, 256>>>();

    dim3 gq((3*Dv+127)/128, TOK/128);
    dim3 g320((Dv+127)/128, TOK/128);
    dim3 gffs((FFv+127)/128, MSEL/128);
    dim3 g320s((Dv+127)/128, MSEL/128);
    const int SMEMG = 73728;
    const int SMEMA = 4*64*APAD*4;

    for (int l=0;l<NLv;l++) {
        k_rmsnorm<<<TOK/8, 256>>>(xp, attn_norm + (size_t)l*Dv, hp, 1);
        k_gemm_tc<<<gq, 256, SMEMG>>>(hp, wtp+OFF_QKV + (size_t)l*960*320, qkvp,
                                      nullptr, nullptr, nullptr, TOK, 3*Dv, Dv, 0);
        k_rope<<<(TOK*Dv+255)/256, 256>>>();
        k_vtr<<<dim3(Sv/32, 2*NHv, Bv), 256>>>();
        k_attn_tc<<<dim3(Sv/64, NHv, Bv), 128, SMEMA>>>();
        k_gemm_tc<<<g320, 256, SMEMG>>>(attp, wtp+OFF_WO + (size_t)l*320*320, xp,
                                        xp, nullptr, nullptr, TOK, Dv, Dv, 1);
        k_router<<<TOK/8, 256>>>(router + (size_t)l*Dv);
        k_topk<<<dim3(Bv, Sv/256), 256>>>();
        k_rmsnorm_sel<<<MSEL/8, 256>>>(mlp_norm + (size_t)l*Dv);
        k_gemm_tc<<<gffs, 256, SMEMG>>>(hp, wtp+OFF_GATE + (size_t)l*FFv*320, g1p,
                                        nullptr, nullptr, nullptr, MSEL, FFv, Dv, 0);
        k_gemm_tc<<<gffs, 256, SMEMG>>>(hp, wtp+OFF_UP + (size_t)l*FFv*320, g2p,
                                        g1p, nullptr, nullptr, MSEL, FFv, Dv, 3);
        k_gemm_tc<<<g320s, 256, SMEMG>>>(g2p, wtp+OFF_DOWN + (size_t)l*320*FFv, xp,
                                         xp, wselp, selp, MSEL, Dv, FFv, 2);
    }
    k_rmsnorm<<<TOK/8, 256>>>(xp, final_norm, out, 0);
}

// round 6
// speedup vs baseline: 3.8847x; 1.0856x over previous
#include <cuda_runtime.h>
#include <cuda_bf16.h>
#include <math.h>

#define Bv 8
#define Sv 2048
#define Dv 320
#define NHv 5
#define HDv 64
#define FFv 864
#define NLv 6
#define NLOOPSv 8
#define TOK (Bv*Sv)
#define KSEL 1638
#define MPAD 1664
#define MSEL (Bv*MPAD)   // 13312

// ---------------- scratch ----------------
__device__ float g_x[TOK*Dv];
__device__ float g_h[TOK*Dv];       // tf32 bits
__device__ float g_qkv[TOK*3*Dv];
__device__ float g_q[Bv*NHv*Sv*HDv];   // tf32 [B][H][S][HD]
__device__ float g_k[Bv*NHv*Sv*HDv];   // tf32 [B][H][S][HD]
__device__ float g_v[Bv*NHv*Sv*HDv];   // tf32 TRANSPOSED [B][H][HD][S]
__device__ float g_att[TOK*Dv];     // tf32 bits
__device__ float g_probs[TOK];
__device__ int   g_sel[MSEL];
__device__ float g_wselc[MSEL];
__device__ float g_g1[TOK*FFv];
__device__ float g_g2[TOK*FFv];

#define OFF_QKV  0
#define OFF_WO   1843200
#define OFF_GATE 2457600
#define OFF_UP   4116480
#define OFF_DOWN 5775360
#define TOTW     7434240
__device__ float g_wt[TOTW];

__device__ __forceinline__ float to_tf32(float x){
    unsigned u; asm("cvt.rna.tf32.f32 %0, %1;" : "=r"(u) : "f"(x));
    return __uint_as_float(u);
}
__device__ __forceinline__ unsigned fbits(float x){ return __float_as_uint(x); }

#define MMA_TF32(acc, A0,A1,A2,A3, B0,B1)                                   \
    asm volatile(                                                           \
        "mma.sync.aligned.m16n8k8.row.col.f32.tf32.tf32.f32 "               \
        "{%0,%1,%2,%3},{%4,%5,%6,%7},{%8,%9},{%0,%1,%2,%3};\n"              \
        : "+f"(acc[0]),"+f"(acc[1]),"+f"(acc[2]),"+f"(acc[3])               \
        : "r"(A0),"r"(A1),"r"(A2),"r"(A3),"r"(B0),"r"(B1))

// ---------------- conversions / embedding ----------------
__global__ void k_cvt(const float* __restrict__ in, float* __restrict__ out, int n){
    int i = blockIdx.x*256 + threadIdx.x;
    if (i < n) out[i] = to_tf32(in[i]);
}

__global__ void k_embed(const int* __restrict__ ids, const int* __restrict__ iter,
                        const float* __restrict__ emb, const float* __restrict__ iter_emb) {
    int idx = blockIdx.x*256 + threadIdx.x;
    if (idx >= TOK*Dv) return;
    int t = idx / Dv, d = idx - t*Dv;
    float v = emb[(size_t)ids[t]*Dv + d];
    int it = iter[0];
    if (it < NLOOPSv) v += iter_emb[it*Dv + d];
    g_x[idx] = v;
}

__global__ void k_clearpad(){
    int i = threadIdx.x;
    if (i < Bv*(MPAD-KSEL)){
        int b = i/(MPAD-KSEL), j = i%(MPAD-KSEL);
        g_sel[b*MPAD + KSEL + j] = -1;
        g_wselc[b*MPAD + KSEL + j] = 0.f;
    }
}

// ---------------- rmsnorm (dense) ----------------
__global__ void k_rmsnorm(const float* __restrict__ in, const float* __restrict__ w,
                          float* __restrict__ out, int tf32out) {
    int gw = (blockIdx.x*256 + threadIdx.x) >> 5;
    int lane = threadIdx.x & 31;
    if (gw >= TOK) return;
    const float* xr = in + (size_t)gw*Dv;
    float v[10]; float ss = 0.f;
    #pragma unroll
    for (int i=0;i<10;i++){ v[i] = xr[lane+32*i]; ss = fmaf(v[i],v[i],ss); }
    #pragma unroll
    for (int o=16;o;o>>=1) ss += __shfl_xor_sync(0xffffffffu, ss, o);
    float inv = rsqrtf(ss*(1.f/Dv) + 1e-6f);
    float* orow = out + (size_t)gw*Dv;
    #pragma unroll
    for (int i=0;i<10;i++){
        float val = w[lane+32*i]*v[i]*inv;
        orow[lane+32*i] = tf32out ? to_tf32(val) : val;
    }
}

// ---------------- rmsnorm over selected rows ----------------
__global__ void k_rmsnorm_sel(const float* __restrict__ w) {
    int gw = (blockIdx.x*256 + threadIdx.x) >> 5;
    int lane = threadIdx.x & 31;
    if (gw >= MSEL) return;
    int tok = g_sel[gw];
    float* orow = g_h + (size_t)gw*Dv;
    if (tok < 0){
        #pragma unroll
        for (int i=0;i<10;i++) orow[lane+32*i] = 0.f;
        return;
    }
    const float* xr = g_x + (size_t)tok*Dv;
    float v[10]; float ss = 0.f;
    #pragma unroll
    for (int i=0;i<10;i++){ v[i] = xr[lane+32*i]; ss = fmaf(v[i],v[i],ss); }
    #pragma unroll
    for (int o=16;o;o>>=1) ss += __shfl_xor_sync(0xffffffffu, ss, o);
    float inv = rsqrtf(ss*(1.f/Dv) + 1e-6f);
    #pragma unroll
    for (int i=0;i<10;i++)
        orow[lane+32*i] = to_tf32(w[lane+32*i]*v[i]*inv);
}

// ---------------- tf32 tensor-core GEMM (128 thr, warp tile 64x64) ----------------
#define CPA(dst, src) asm volatile("cp.async.cg.shared.global [%0], [%1], 16;\n" :: "r"(dst), "l"(src))
#define CPAZ(dst, src, sz) asm volatile("cp.async.cg.shared.global [%0], [%1], 16, %2;\n" :: "r"(dst), "l"(src), "r"(sz))

__global__ __launch_bounds__(128) void k_gemm_tc(
    const float* __restrict__ A, const float* __restrict__ W, float* __restrict__ C,
    const float* __restrict__ aux, const float* __restrict__ rowscale,
    const int* __restrict__ sel,
    int M, int N, int K, int ep)
{
    extern __shared__ float sm[];
    const int SA = 128*36;
    unsigned base = (unsigned)__cvta_generic_to_shared(sm);
    unsigned Asb[2] = { base, base + SA*4u };
    unsigned Wsb[2] = { base + 2u*SA*4u, base + 3u*SA*4u };
    float* Asp[2] = { sm, sm + SA };
    float* Wsp[2] = { sm + 2*SA, sm + 3*SA };

    int tid = threadIdx.x;
    int lane = tid & 31, warp = tid >> 5;
    int wm = warp >> 1, wn = warp & 1;           // 2x2 warps, 64x64 each
    int m0 = blockIdx.y*128, n0 = blockIdx.x*128;

    int lrow = tid >> 3;        // 0..15
    int c16  = tid & 7;
    const float* Ag = A + (size_t)(m0 + lrow)*K + c16*4;
    int wr0 = n0 + lrow;

    float acc[4][8][4];
    #pragma unroll
    for (int i=0;i<4;i++)
        #pragma unroll
        for (int j=0;j<8;j++)
            #pragma unroll
            for (int c=0;c<4;c++) acc[i][j][c]=0.f;

    int nkb = K >> 5;

    #define LOADTILE(buf, k0) do {                                              \
        _Pragma("unroll")                                                       \
        for (int i=0;i<8;i++){                                                  \
            int r = lrow + 16*i;                                                \
            unsigned d = Asb[buf] + (unsigned)((r*36 + c16*4)*4);               \
            CPA(d, Ag + (size_t)(16*i)*K + (k0));                               \
        }                                                                       \
        _Pragma("unroll")                                                       \
        for (int i=0;i<8;i++){                                                  \
            int r = lrow + 16*i;                                                \
            int wr = wr0 + 16*i;                                                \
            unsigned sz = (wr < N) ? 16u : 0u;                                  \
            const float* src = W + (size_t)(wr < N ? wr : 0)*K + (k0) + c16*4;  \
            unsigned d = Wsb[buf] + (unsigned)((r*36 + c16*4)*4);               \
            CPAZ(d, src, sz);                                                   \
        }                                                                       \
    } while(0)

    LOADTILE(0, 0);
    asm volatile("cp.async.commit_group;\n");

    int buf = 0;
    int lr = lane >> 2, lc = lane & 3;
    for (int kb=0; kb<nkb; kb++){
        if (kb+1 < nkb){
            LOADTILE(buf^1, (kb+1)*32);
            asm volatile("cp.async.commit_group;\n");
            asm volatile("cp.async.wait_group 1;\n");
        } else {
            asm volatile("cp.async.wait_group 0;\n");
        }
        __syncthreads();

        const float* Ab = Asp[buf];
        const float* Wb = Wsp[buf];
        #pragma unroll
        for (int ks=0; ks<4; ks++){
            unsigned a[4][4], b[8][2];
            #pragma unroll
            for (int mf=0; mf<4; mf++){
                const float* p = Ab + (wm*64 + mf*16 + lr)*36 + ks*8 + lc;
                a[mf][0] = fbits(p[0]);
                a[mf][1] = fbits(p[8*36]);
                a[mf][2] = fbits(p[4]);
                a[mf][3] = fbits(p[8*36+4]);
            }
            #pragma unroll
            for (int nf=0; nf<8; nf++){
                const float* p = Wb + (wn*64 + nf*8 + lr)*36 + ks*8 + lc;
                b[nf][0] = fbits(p[0]);
                b[nf][1] = fbits(p[4]);
            }
            #pragma unroll
            for (int mf=0; mf<4; mf++)
                #pragma unroll
                for (int nf=0; nf<8; nf++)
                    MMA_TF32(acc[mf][nf], a[mf][0],a[mf][1],a[mf][2],a[mf][3],
                             b[nf][0], b[nf][1]);
        }
        buf ^= 1;
        __syncthreads();
    }

    #pragma unroll
    for (int mf=0; mf<4; mf++){
        #pragma unroll
        for (int nf=0; nf<8; nf++){
            int mbase = m0 + wm*64 + mf*16 + lr;
            int nbase = n0 + wn*64 + nf*8 + lc*2;
            #pragma unroll
            for (int c=0;c<4;c++){
                int m = mbase + (c>=2 ? 8 : 0);
                int n = nbase + (c&1);
                if (n < N){
                    float v = acc[mf][nf][c];
                    if (ep==2){
                        int tok = sel[m];
                        if (tok >= 0){
                            size_t o = (size_t)tok*N + n;
                            C[o] = aux[o] + rowscale[m]*v;
                        }
                    } else {
                        size_t o = (size_t)m*N + n;
                        if (ep==0) C[o] = v;
                        else if (ep==1) C[o] = aux[o] + v;
                        else { float g = aux[o]; C[o] = to_tf32(g * v / (1.f + expf(-g))); }
                    }
                }
            }
        }
    }
}

// ---------------- RoPE (q,k only, tf32 out) ----------------
__global__ void k_rope() {
    int idx = blockIdx.x*256 + threadIdx.x;
    if (idx >= TOK*Dv) return;
    int t = idx / Dv;
    int rem = idx - t*Dv;
    int h = rem >> 6, d = rem & 63;
    int s = t & (Sv-1), b = t >> 11;
    const float* base = g_qkv + (size_t)t*(3*Dv) + h*HDv;
    float qv = base[d], kv = base[Dv + d];
    int i2 = d & 31;
    float freq = expf(-(float)(2*i2) * (9.210340371976184f/64.0f));
    float ang = (float)s * freq;
    float sn, cs; sincosf(ang, &sn, &cs);
    float qr, kr;
    if (d < 32) { qr = -base[d+32];      kr = -base[Dv+d+32]; }
    else        { qr =  base[d-32];      kr =  base[Dv+d-32]; }
    size_t o = (((size_t)b*NHv + h)*Sv + s)*HDv + d;
    g_q[o] = to_tf32(qv*cs + qr*sn);
    g_k[o] = to_tf32(kv*cs + kr*sn);
}

// ---------------- V transpose -> [B][H][HD][S], tf32 ----------------
__global__ __launch_bounds__(256) void k_vtr() {
    __shared__ float t[32][33];
    int st = blockIdx.x*32;
    int dh = blockIdx.y;
    int h = dh >> 1, dt = (dh & 1)*32;
    int b = blockIdx.z;
    int lx = threadIdx.x & 31, ly = threadIdx.x >> 5;
    const float* src = g_qkv + (size_t)(b*Sv)*(3*Dv) + 2*Dv + h*HDv + dt + lx;
    #pragma unroll
    for (int r=0;r<4;r++){
        int s = st + ly + r*8;
        t[ly+r*8][lx] = src[(size_t)s*(3*Dv)];
    }
    __syncthreads();
    float* dst = g_v + (((size_t)b*NHv + h)*HDv)*Sv + st + lx;
    #pragma unroll
    for (int r=0;r<4;r++){
        int d = dt + ly + r*8;
        dst[(size_t)d*Sv] = to_tf32(t[lx][ly+r*8]);
    }
}

// ---------------- tf32 tensor-core flash attention ----------------
#define APAD 68
__global__ __launch_bounds__(128) void k_attn_tc() {
    extern __shared__ float sm[];
    float* Qs = sm;
    float* Ks = sm + 64*APAD;
    float* Vt = sm + 2*64*APAD;
    float* Ps = sm + 3*64*APAD;
    int qt = gridDim.x - 1 - blockIdx.x;   // heavy tiles first
    int h = blockIdx.y, b = blockIdx.z;
    int tid = threadIdx.x, lane = tid & 31, warp = tid >> 5;
    int lr = lane >> 2, lc = lane & 3;
    const size_t headoff = ((size_t)b*NHv + h)*(size_t)Sv*HDv;
    const float* Qg = g_q + headoff + (size_t)qt*64*HDv;
    const float* Kg0 = g_k + headoff;
    const float* Vg0 = g_v + headoff;

    #pragma unroll
    for (int i=0;i<8;i++){
        int idx = (tid + i*128)*4;
        int row = idx >> 6, col = idx & 63;
        *(float4*)(Qs + row*APAD + col) = *(const float4*)(Qg + idx);
    }

    float o[8][4];
    #pragma unroll
    for (int nt=0;nt<8;nt++)
        #pragma unroll
        for (int c=0;c<4;c++) o[nt][c]=0.f;
    float mr0=-1e30f, mr1=-1e30f, ls0=0.f, ls1=0.f;
    int qrow = qt*64 + warp*16 + lr;

    for (int t0=0; t0<=qt; t0++){
        __syncthreads();
        const float* Kg = Kg0 + (size_t)t0*64*HDv;
        #pragma unroll
        for (int i=0;i<8;i++){
            int idx = (tid + i*128)*4;
            int row = idx >> 6, col = idx & 63;
            *(float4*)(Ks + row*APAD + col) = *(const float4*)(Kg + idx);
            *(float4*)(Vt + row*APAD + col) = *(const float4*)(Vg0 + (size_t)row*Sv + t0*64 + col);
        }
        __syncthreads();

        float sacc[8][4];
        #pragma unroll
        for (int nt=0;nt<8;nt++)
            #pragma unroll
            for (int c=0;c<4;c++) sacc[nt][c]=0.f;
        #pragma unroll
        for (int ks=0; ks<8; ks++){
            const float* ap = Qs + (warp*16 + lr)*APAD + ks*8 + lc;
            unsigned a0=fbits(ap[0]), a1=fbits(ap[8*APAD]),
                     a2=fbits(ap[4]), a3=fbits(ap[8*APAD+4]);
            #pragma unroll
            for (int nt=0; nt<8; nt++){
                const float* bp = Ks + (nt*8 + lr)*APAD + ks*8 + lc;
                MMA_TF32(sacc[nt], a0,a1,a2,a3, fbits(bp[0]), fbits(bp[4]));
            }
        }

        bool diag = (t0 == qt);
        float mt0=-1e30f, mt1=-1e30f;
        #pragma unroll
        for (int nt=0;nt<8;nt++){
            #pragma unroll
            for (int c=0;c<4;c++){
                float s = sacc[nt][c]*0.125f;
                if (diag){
                    int col = t0*64 + nt*8 + lc*2 + (c&1);
                    int row = qrow + ((c>=2)?8:0);
                    if (col > row) s = -1e30f;
                }
                sacc[nt][c] = s;
                if (c>=2) mt1 = fmaxf(mt1, s); else mt0 = fmaxf(mt0, s);
            }
        }
        mt0 = fmaxf(mt0, __shfl_xor_sync(0xffffffffu, mt0, 1));
        mt0 = fmaxf(mt0, __shfl_xor_sync(0xffffffffu, mt0, 2));
        mt1 = fmaxf(mt1, __shfl_xor_sync(0xffffffffu, mt1, 1));
        mt1 = fmaxf(mt1, __shfl_xor_sync(0xffffffffu, mt1, 2));
        float mn0 = fmaxf(mr0, mt0), mn1 = fmaxf(mr1, mt1);
        float sc0 = __expf(mr0 - mn0), sc1 = __expf(mr1 - mn1);
        ls0 *= sc0; ls1 *= sc1;
        #pragma unroll
        for (int nt=0;nt<8;nt++){
            o[nt][0]*=sc0; o[nt][1]*=sc0; o[nt][2]*=sc1; o[nt][3]*=sc1;
        }
        mr0 = mn0; mr1 = mn1;

        float* pr0 = Ps + (warp*16 + lr)*APAD;
        float* pr1 = pr0 + 8*APAD;
        #pragma unroll
        for (int nt=0;nt<8;nt++){
            int col = nt*8 + lc*2;
            float p0 = __expf(sacc[nt][0] - mn0);
            float p1 = __expf(sacc[nt][1] - mn0);
            float p2 = __expf(sacc[nt][2] - mn1);
            float p3 = __expf(sacc[nt][3] - mn1);
            ls0 += p0 + p1; ls1 += p2 + p3;
            pr0[col]   = to_tf32(p0);
            pr0[col+1] = to_tf32(p1);
            pr1[col]   = to_tf32(p2);
            pr1[col+1] = to_tf32(p3);
        }
        __syncwarp();

        #pragma unroll
        for (int ks=0; ks<8; ks++){
            const float* ap = Ps + (warp*16 + lr)*APAD + ks*8 + lc;
            unsigned a0=fbits(ap[0]), a1=fbits(ap[8*APAD]),
                     a2=fbits(ap[4]), a3=fbits(ap[8*APAD+4]);
            #pragma unroll
            for (int nt=0; nt<8; nt++){
                const float* bp = Vt + (nt*8 + lr)*APAD + ks*8 + lc;
                MMA_TF32(o[nt], a0,a1,a2,a3, fbits(bp[0]), fbits(bp[4]));
            }
        }
    }

    ls0 += __shfl_xor_sync(0xffffffffu, ls0, 1);
    ls0 += __shfl_xor_sync(0xffffffffu, ls0, 2);
    ls1 += __shfl_xor_sync(0xffffffffu, ls1, 1);
    ls1 += __shfl_xor_sync(0xffffffffu, ls1, 2);
    float inv0 = 1.f/ls0, inv1 = 1.f/ls1;
    int tok0 = b*Sv + qt*64 + warp*16 + lr;
    float* out0 = g_att + (size_t)tok0*Dv + h*HDv;
    float* out1 = out0 + 8*(size_t)Dv;
    #pragma unroll
    for (int nt=0;nt<8;nt++){
        int col = nt*8 + lc*2;
        out0[col]   = to_tf32(o[nt][0]*inv0);
        out0[col+1] = to_tf32(o[nt][1]*inv0);
        out1[col]   = to_tf32(o[nt][2]*inv1);
        out1[col+1] = to_tf32(o[nt][3]*inv1);
    }
}

// ---------------- router ----------------
__global__ void k_router(const float* __restrict__ rw) {
    int gw = (blockIdx.x*256 + threadIdx.x) >> 5;
    int lane = threadIdx.x & 31;
    if (gw >= TOK) return;
    const float* xr = g_x + (size_t)gw*Dv;
    float s = 0.f;
    #pragma unroll
    for (int i=0;i<10;i++) s = fmaf(xr[lane+32*i], rw[lane+32*i], s);
    #pragma unroll
    for (int o=16;o;o>>=1) s += __shfl_xor_sync(0xffffffffu, s, o);
    if (lane==0) g_probs[gw] = 1.f/(1.f+expf(-s));
}

// ---------------- exact top-k -> compact selection ----------------
__global__ __launch_bounds__(256) void k_topk() {
    __shared__ float p[Sv];
    int b = blockIdx.x, part = blockIdx.y;
    int tid = threadIdx.x;
    for (int i=tid;i<Sv;i+=256) p[i] = g_probs[b*Sv+i];
    __syncthreads();
    int i = part*256 + tid;
    float pi = p[i];
    int cnt = 0;
    #pragma unroll 8
    for (int j=0;j<Sv;j++) {
        float pj = p[j];
        cnt += (pj > pi) || (pj == pi && j < i);
    }
    if (cnt < KSEL){
        g_sel[b*MPAD + cnt] = b*Sv + i;
        g_wselc[b*MPAD + cnt] = pi;
    }
}

// ---------------- driver ----------------
extern "C" void kernel_launch(void* const* d_in, const int* in_sizes, int n_in,
                              void* d_out, int out_size) {
    const int*   ids        = (const int*)d_in[0];
    const int*   iter       = (const int*)d_in[1];
    const float* emb        = (const float*)d_in[2];
    const float* iter_emb   = (const float*)d_in[3];
    const float* attn_norm  = (const float*)d_in[4];
    const float* Wqkv       = (const float*)d_in[5];
    const float* wo         = (const float*)d_in[6];
    const float* router     = (const float*)d_in[7];
    const float* mlp_norm   = (const float*)d_in[8];
    const float* gatew      = (const float*)d_in[9];
    const float* upw        = (const float*)d_in[10];
    const float* downw      = (const float*)d_in[11];
    const float* final_norm = (const float*)d_in[12];
    float* out = (float*)d_out;

    float *xp,*hp,*qkvp,*attp,*g1p,*g2p,*wselp,*wtp;
    int *selp;
    cudaGetSymbolAddress((void**)&xp,   g_x);
    cudaGetSymbolAddress((void**)&hp,   g_h);
    cudaGetSymbolAddress((void**)&qkvp, g_qkv);
    cudaGetSymbolAddress((void**)&attp, g_att);
    cudaGetSymbolAddress((void**)&g1p,  g_g1);
    cudaGetSymbolAddress((void**)&g2p,  g_g2);
    cudaGetSymbolAddress((void**)&wselp,g_wselc);
    cudaGetSymbolAddress((void**)&selp, g_sel);
    cudaGetSymbolAddress((void**)&wtp,  g_wt);

    cudaFuncSetAttribute(k_attn_tc, cudaFuncAttributeMaxDynamicSharedMemorySize, 4*64*APAD*4);
    cudaFuncSetAttribute(k_gemm_tc, cudaFuncAttributeMaxDynamicSharedMemorySize, 73728);

    k_cvt<<<(1843200+255)/256,256>>>(Wqkv,  wtp+OFF_QKV,  1843200);
    k_cvt<<<(614400+255)/256, 256>>>(wo,    wtp+OFF_WO,   614400);
    k_cvt<<<(1658880+255)/256,256>>>(gatew, wtp+OFF_GATE, 1658880);
    k_cvt<<<(1658880+255)/256,256>>>(upw,   wtp+OFF_UP,   1658880);
    k_cvt<<<(1658880+255)/256,256>>>(downw, wtp+OFF_DOWN, 1658880);

    k_embed<<<(TOK*Dv+255)/256, 256>>>(ids, iter, emb, iter_emb);
    k_clearpad<<<1, 256>>>();

    dim3 gq((3*Dv+127)/128, TOK/128);
    dim3 g320((Dv+127)/128, TOK/128);
    dim3 gffs((FFv+127)/128, MSEL/128);
    dim3 g320s((Dv+127)/128, MSEL/128);
    const int SMEMG = 73728;
    const int SMEMA = 4*64*APAD*4;

    for (int l=0;l<NLv;l++) {
        k_rmsnorm<<<TOK/8, 256>>>(xp, attn_norm + (size_t)l*Dv, hp, 1);
        k_gemm_tc<<<gq, 128, SMEMG>>>(hp, wtp+OFF_QKV + (size_t)l*960*320, qkvp,
                                      nullptr, nullptr, nullptr, TOK, 3*Dv, Dv, 0);
        k_rope<<<(TOK*Dv+255)/256, 256>>>();
        k_vtr<<<dim3(Sv/32, 2*NHv, Bv), 256>>>();
        k_attn_tc<<<dim3(Sv/64, NHv, Bv), 128, SMEMA>>>();
        k_gemm_tc<<<g320, 128, SMEMG>>>(attp, wtp+OFF_WO + (size_t)l*320*320, xp,
                                        xp, nullptr, nullptr, TOK, Dv, Dv, 1);
        k_router<<<TOK/8, 256>>>(router + (size_t)l*Dv);
        k_topk<<<dim3(Bv, Sv/256), 256>>>();
        k_rmsnorm_sel<<<MSEL/8, 256>>>(mlp_norm + (size_t)l*Dv);
        k_gemm_tc<<<gffs, 128, SMEMG>>>(hp, wtp+OFF_GATE + (size_t)l*FFv*320, g1p,
                                        nullptr, nullptr, nullptr, MSEL, FFv, Dv, 0);
        k_gemm_tc<<<gffs, 128, SMEMG>>>(hp, wtp+OFF_UP + (size_t)l*FFv*320, g2p,
                                        g1p, nullptr, nullptr, MSEL, FFv, Dv, 3);
        k_gemm_tc<<<g320s, 128, SMEMG>>>(g2p, wtp+OFF_DOWN + (size_t)l*320*FFv, xp,
                                         xp, wselp, selp, MSEL, Dv, FFv, 2);
    }
    k_rmsnorm<<<TOK/8, 256>>>(xp, final_norm, out, 0);
}